// round 7
// baseline (speedup 1.0000x reference)
#include <cuda_runtime.h>
#include <cstdint>

#define NN   100000
#define EE   1600000
#define INC  256
#define HID  128
#define OUTC 64
#define SCAN_B 128
#define MAXBLK 1024

// -------- scratch (__device__ globals; allocation is forbidden) --------
static __device__ __align__(256) int   d_degi[NN];
static __device__ __align__(256) int   d_off [NN + 1];
static __device__ __align__(256) int   d_cur [NN];
static __device__ __align__(256) int   d_csr [EE];
static __device__ __align__(256) int   d_bsum [MAXBLK];
static __device__ __align__(256) int   d_bsum2[MAXBLK];
static __device__ __align__(256) float d_dinv[NN];
static __device__ __align__(256) float d_Hs [(size_t)NN * HID];  // x@W1 (unscaled)
static __device__ __align__(256) float d_Gs [(size_t)NN * HID];  // dinv*(H1@Wcat)
static __device__ __align__(256) float d_Wcat[HID * HID];

// ---------------- packed f32x2 helpers ----------------
static __device__ __forceinline__ void ffma2(unsigned long long& d,
                                             unsigned long long a,
                                             unsigned long long b) {
    asm("fma.rn.f32x2 %0, %1, %2, %0;" : "+l"(d) : "l"(a), "l"(b));
}
static __device__ __forceinline__ unsigned long long bcast2(float f) {
    unsigned long long r;
    asm("mov.b64 %0, {%1, %1};" : "=l"(r) : "f"(f));
    return r;
}
static __device__ __forceinline__ unsigned long long pack2(float a, float b) {
    unsigned long long r;
    asm("mov.b64 %0, {%1, %2};" : "=l"(r) : "f"(a), "f"(b));
    return r;
}

// ---------------- graph preprocessing ----------------
__global__ void k_zero_deg(int n) {
    int i = blockIdx.x * blockDim.x + threadIdx.x;
    if (i < n) d_degi[i] = 0;
}
__global__ void k_degcnt(const int* __restrict__ dst, int e) {
    int i = blockIdx.x * blockDim.x + threadIdx.x;
    if (i < e) atomicAdd(&d_degi[dst[i]], 1);
}
__global__ void k_dinv(int n) {
    int i = blockIdx.x * blockDim.x + threadIdx.x;
    if (i < n) d_dinv[i] = rsqrtf((float)(d_degi[i] + 1));  // +1 self loop
}
__global__ void k_scanA(int n) {
    __shared__ int sm[SCAN_B];
    int b = blockIdx.x, t = threadIdx.x, gi = b * SCAN_B + t;
    int v = (gi < n) ? d_degi[gi] : 0;
    sm[t] = v; __syncthreads();
    #pragma unroll
    for (int s = 1; s < SCAN_B; s <<= 1) {
        int u = (t >= s) ? sm[t - s] : 0;
        __syncthreads(); sm[t] += u; __syncthreads();
    }
    if (gi < n) d_off[gi + 1] = sm[t];
    if (t == SCAN_B - 1) d_bsum[b] = sm[t];
}
__global__ void k_scanB(int nblk) {
    __shared__ int sm[MAXBLK];
    int t = threadIdx.x;
    int v = (t < nblk) ? d_bsum[t] : 0;
    sm[t] = v; __syncthreads();
    #pragma unroll
    for (int s = 1; s < MAXBLK; s <<= 1) {
        int u = (t >= s) ? sm[t - s] : 0;
        __syncthreads(); sm[t] += u; __syncthreads();
    }
    if (t < nblk) d_bsum2[t] = sm[t] - v;
    if (t == 0) d_off[0] = 0;
}
__global__ void k_scanC(int n) {
    int b = blockIdx.x, t = threadIdx.x, gi = b * SCAN_B + t;
    if (gi < n) {
        int o = d_off[gi + 1] + d_bsum2[b];
        d_off[gi + 1] = o;
        d_cur[gi] = o - d_degi[gi];
    }
}
__global__ void k_scatter(const int* __restrict__ src,
                          const int* __restrict__ dst, int e) {
    int i = blockIdx.x * blockDim.x + threadIdx.x;
    if (i < e) {
        int d = dst[i];
        int pos = atomicAdd(&d_cur[d], 1);
        d_csr[pos] = src[i];
    }
}
__global__ void k_build_wcat(const float* __restrict__ Wmu,
                             const float* __restrict__ Wlv) {
    int i = blockIdx.x * blockDim.x + threadIdx.x;
    if (i < HID * HID) {
        int k = i / HID, c = i % HID;
        d_Wcat[i] = (c < OUTC) ? Wmu[k * OUTC + c] : Wlv[k * OUTC + (c - OUTC)];
    }
}

// -------- SGEMM (FFMA2): C[M,128] = A[M,K] @ B[K,128] (unscaled) --------
template <int K>
__global__ void __launch_bounds__(256)
k_gemm(const float* __restrict__ A, const float* __restrict__ B,
       float* __restrict__ C, int M) {
    constexpr int BM = 128, BN = 128, BK = 16;
    __shared__ float As[BK][BM + 2];
    __shared__ float Bs[BK][BN];

    const int tid = threadIdx.x;
    const int tx  = tid & 15;
    const int ty  = tid >> 4;
    const int row0 = blockIdx.x * BM;
    const int arow = tid >> 2;
    const int acol = (tid & 3) * 4;

    unsigned long long acc2[4][8] = {};

    for (int k0 = 0; k0 < K; k0 += BK) {
        #pragma unroll
        for (int i = 0; i < 2; i++) {
            int r  = arow + i * 64;
            int gr = row0 + r;
            float4 av = (gr < M)
                ? *(const float4*)(A + (size_t)gr * K + k0 + acol)
                : make_float4(0.f, 0.f, 0.f, 0.f);
            As[acol + 0][r] = av.x;
            As[acol + 1][r] = av.y;
            As[acol + 2][r] = av.z;
            As[acol + 3][r] = av.w;
        }
        #pragma unroll
        for (int i = 0; i < 2; i++) {
            int idx  = tid + i * 256;
            int brow = idx >> 5;
            int bcol = (idx & 31) * 4;
            *(float4*)&Bs[brow][bcol] =
                *(const float4*)(B + (size_t)(k0 + brow) * BN + bcol);
        }
        __syncthreads();

        #pragma unroll
        for (int kk = 0; kk < BK; kk++) {
            unsigned long long a2[4];
            const unsigned long long* ap =
                (const unsigned long long*)&As[kk][ty * 8];
            #pragma unroll
            for (int j = 0; j < 4; j++) a2[j] = ap[j];
            float bv[8];
            *(float4*)&bv[0] = *(float4*)&Bs[kk][tx * 8];
            *(float4*)&bv[4] = *(float4*)&Bs[kk][tx * 8 + 4];
            unsigned long long b2[8];
            #pragma unroll
            for (int i = 0; i < 8; i++) b2[i] = bcast2(bv[i]);
            #pragma unroll
            for (int j = 0; j < 4; j++)
                #pragma unroll
                for (int i = 0; i < 8; i++)
                    ffma2(acc2[j][i], a2[j], b2[i]);
        }
        __syncthreads();
    }

    #pragma unroll
    for (int j = 0; j < 4; j++) {
        int r0 = row0 + ty * 8 + 2 * j;
        float lo[8], hi[8];
        #pragma unroll
        for (int i = 0; i < 8; i++) {
            lo[i] = __uint_as_float((uint32_t)(acc2[j][i] & 0xffffffffull));
            hi[i] = __uint_as_float((uint32_t)(acc2[j][i] >> 32));
        }
        if (r0 < M) {
            float* cp = C + (size_t)r0 * BN + tx * 8;
            *(float4*)cp       = make_float4(lo[0], lo[1], lo[2], lo[3]);
            *(float4*)(cp + 4) = make_float4(lo[4], lo[5], lo[6], lo[7]);
        }
        if (r0 + 1 < M) {
            float* cp = C + (size_t)(r0 + 1) * BN + tx * 8;
            *(float4*)cp       = make_float4(hi[0], hi[1], hi[2], hi[3]);
            *(float4*)(cp + 4) = make_float4(hi[4], hi[5], hi[6], hi[7]);
        }
    }
}

// ====== FUSED: agg1 (gather into smem) + GEMM2 (H1tile @ Wcat) ======
// Gs[row] = dinv[row] * ( H1tile[row] @ Wcat ),
// H1tile[r] = leaky( dinv[r]*(Σ_nbr dinv[s]*Hs[s] + dinv[r]*Hs[r]) + b1 )
__global__ void __launch_bounds__(256)
k_fused_agg_gemm(const float* __restrict__ Wc, float* __restrict__ Gs,
                 const float* __restrict__ b1, int n) {
    extern __shared__ float smem[];
    float* sH = smem;                   // 128 x 128
    float* Bs = smem + 128 * 128;       // 16 x 128

    const int tid = threadIdx.x;
    const int wid = tid >> 5;
    const int lane = tid & 31;
    const int row0 = blockIdx.x * 128;

    // ---- phase 1: gather 128-row H1 tile into sH ----
    {
        const float4* base = (const float4*)d_Hs;
        float4 b4 = *(const float4*)(b1 + lane * 4);
        for (int i = 0; i < 16; i++) {
            int lr = wid * 16 + i;
            int d  = row0 + lr;
            float4 r = make_float4(0.f, 0.f, 0.f, 0.f);
            if (d < n) {
                float sd = d_dinv[d];
                float4 acc = base[(size_t)d * 32 + lane];   // self
                acc.x *= sd; acc.y *= sd; acc.z *= sd; acc.w *= sd;
                int beg = d_off[d], end = d_off[d + 1];
                for (int k = beg; k < end; k += 32) {
                    int rem = end - k;
                    int   s  = (lane < rem) ? d_csr[k + lane] : 0;
                    float sv = (lane < rem) ? d_dinv[s] : 0.f;
                    int cnt = rem < 32 ? rem : 32;
                    for (int j = 0; j < cnt; j++) {
                        int   sj = __shfl_sync(0xffffffffu, s,  j);
                        float dv = __shfl_sync(0xffffffffu, sv, j);
                        float4 v = base[(size_t)sj * 32 + lane];
                        acc.x += v.x * dv; acc.y += v.y * dv;
                        acc.z += v.z * dv; acc.w += v.w * dv;
                    }
                }
                r.x = acc.x * sd + b4.x; r.y = acc.y * sd + b4.y;
                r.z = acc.z * sd + b4.z; r.w = acc.w * sd + b4.w;
                r.x = r.x >= 0.f ? r.x : 0.01f * r.x;
                r.y = r.y >= 0.f ? r.y : 0.01f * r.y;
                r.z = r.z >= 0.f ? r.z : 0.01f * r.z;
                r.w = r.w >= 0.f ? r.w : 0.01f * r.w;
            }
            *(float4*)(sH + lr * HID + lane * 4) = r;
        }
    }
    __syncthreads();

    // ---- phase 2: GEMM, A = sH (column broadcasts), B staged in Bs ----
    const int tx = tid & 15;
    const int ty = tid >> 4;
    unsigned long long acc2[4][8] = {};

    for (int k0 = 0; k0 < HID; k0 += 16) {
        #pragma unroll
        for (int i = 0; i < 2; i++) {
            int idx  = tid + i * 256;
            int brow = idx >> 5;
            int bcol = (idx & 31) * 4;
            *(float4*)&Bs[brow * HID + bcol] =
                *(const float4*)(Wc + (size_t)(k0 + brow) * HID + bcol);
        }
        __syncthreads();
        #pragma unroll
        for (int kk = 0; kk < 16; kk++) {
            unsigned long long a2[4];
            #pragma unroll
            for (int j = 0; j < 4; j++) {
                float a0 = sH[(ty * 8 + 2 * j)     * HID + k0 + kk];
                float a1 = sH[(ty * 8 + 2 * j + 1) * HID + k0 + kk];
                a2[j] = pack2(a0, a1);
            }
            float bv[8];
            *(float4*)&bv[0] = *(float4*)&Bs[kk * HID + tx * 8];
            *(float4*)&bv[4] = *(float4*)&Bs[kk * HID + tx * 8 + 4];
            unsigned long long b2[8];
            #pragma unroll
            for (int i = 0; i < 8; i++) b2[i] = bcast2(bv[i]);
            #pragma unroll
            for (int j = 0; j < 4; j++)
                #pragma unroll
                for (int i = 0; i < 8; i++)
                    ffma2(acc2[j][i], a2[j], b2[i]);
        }
        __syncthreads();
    }

    // ---- epilogue: scale rows by dinv, store Gs ----
    #pragma unroll
    for (int j = 0; j < 4; j++) {
        int r0 = row0 + ty * 8 + 2 * j;
        float lo[8], hi[8];
        #pragma unroll
        for (int i = 0; i < 8; i++) {
            lo[i] = __uint_as_float((uint32_t)(acc2[j][i] & 0xffffffffull));
            hi[i] = __uint_as_float((uint32_t)(acc2[j][i] >> 32));
        }
        if (r0 < n) {
            float s = d_dinv[r0];
            float* cp = Gs + (size_t)r0 * HID + tx * 8;
            *(float4*)cp       = make_float4(lo[0]*s, lo[1]*s, lo[2]*s, lo[3]*s);
            *(float4*)(cp + 4) = make_float4(lo[4]*s, lo[5]*s, lo[6]*s, lo[7]*s);
        }
        if (r0 + 1 < n) {
            float s = d_dinv[r0 + 1];
            float* cp = Gs + (size_t)(r0 + 1) * HID + tx * 8;
            *(float4*)cp       = make_float4(hi[0]*s, hi[1]*s, hi[2]*s, hi[3]*s);
            *(float4*)(cp + 4) = make_float4(hi[4]*s, hi[5]*s, hi[6]*s, hi[7]*s);
        }
    }
}

// -------- agg2: warp per node, Gs pre-scaled rows, split mu|lv --------
__global__ void k_agg2(const float* __restrict__ bmu,
                       const float* __restrict__ blv,
                       float* __restrict__ mu, float* __restrict__ lv, int n) {
    int d = (blockIdx.x * blockDim.x + threadIdx.x) >> 5;
    int lane = threadIdx.x & 31;
    if (d >= n) return;
    const float4* base = (const float4*)d_Gs;
    float4 acc = base[(size_t)d * 32 + lane];           // self (pre-scaled)
    int beg = d_off[d], end = d_off[d + 1];
    for (int k = beg; k < end; k += 32) {
        int rem = end - k;
        int s = (lane < rem) ? d_csr[k + lane] : 0;
        int cnt = rem < 32 ? rem : 32;
        for (int j = 0; j < cnt; j++) {
            int sj = __shfl_sync(0xffffffffu, s, j);
            float4 v = base[(size_t)sj * 32 + lane];
            acc.x += v.x; acc.y += v.y; acc.z += v.z; acc.w += v.w;
        }
    }
    float sc = d_dinv[d];
    float4 bb = (lane < 16) ? *(const float4*)(bmu + lane * 4)
                            : *(const float4*)(blv + (lane - 16) * 4);
    float4 r;
    r.x = acc.x * sc + bb.x; r.y = acc.y * sc + bb.y;
    r.z = acc.z * sc + bb.z; r.w = acc.w * sc + bb.w;
    float* p = (lane < 16) ? (mu + (size_t)d * OUTC + lane * 4)
                           : (lv + (size_t)d * OUTC + (lane - 16) * 4);
    *(float4*)p = r;
}

// ---------------- launch ----------------
extern "C" void kernel_launch(void* const* d_in, const int* in_sizes, int n_in,
                              void* d_out, int out_size) {
    const float* x   = (const float*)d_in[0];
    const int*   ei  = (const int*)d_in[1];     // int32 (JAX x64 disabled)
    const float* W1  = (const float*)d_in[2];
    const float* b1  = (const float*)d_in[3];
    const float* Wmu = (const float*)d_in[4];
    const float* bmu = (const float*)d_in[5];
    const float* Wlv = (const float*)d_in[6];
    const float* blv = (const float*)d_in[7];

    const int e = in_sizes[1] / 2;
    const int n = in_sizes[0] / INC;
    const int* src = ei;
    const int* dst = ei + e;

    float* mu = (float*)d_out;
    float* lv = mu + (size_t)n * OUTC;

    float *hs_p, *gs_p, *wcat_p;
    cudaGetSymbolAddress((void**)&hs_p,   d_Hs);
    cudaGetSymbolAddress((void**)&gs_p,   d_Gs);
    cudaGetSymbolAddress((void**)&wcat_p, d_Wcat);

    static cudaStream_t s1 = nullptr;
    static cudaEvent_t  evFork = nullptr, evJoin = nullptr;
    static bool attrSet = false;
    const int FUSED_SMEM = (128 * 128 + 16 * 128) * (int)sizeof(float); // 72KB
    if (!s1) {
        cudaStreamCreateWithFlags(&s1, cudaStreamNonBlocking);
        cudaEventCreateWithFlags(&evFork, cudaEventDisableTiming);
        cudaEventCreateWithFlags(&evJoin, cudaEventDisableTiming);
    }
    if (!attrSet) {
        cudaFuncSetAttribute(k_fused_agg_gemm,
                             cudaFuncAttributeMaxDynamicSharedMemorySize,
                             FUSED_SMEM);
        attrSet = true;
    }

    const int T = 256;
    const int nblk = (n + SCAN_B - 1) / SCAN_B;
    const int gblk = (n + 127) / 128;

    // fork: graph prep on s1 concurrent with GEMM1 on main stream
    cudaEventRecord(evFork, 0);
    cudaStreamWaitEvent(s1, evFork, 0);

    k_zero_deg<<<(n + T - 1) / T, T, 0, s1>>>(n);
    k_degcnt<<<(e + T - 1) / T, T, 0, s1>>>(dst, e);
    k_dinv<<<(n + T - 1) / T, T, 0, s1>>>(n);
    k_scanA<<<nblk, SCAN_B, 0, s1>>>(n);
    k_scanB<<<1, MAXBLK, 0, s1>>>(nblk);
    k_scanC<<<nblk, SCAN_B, 0, s1>>>(n);
    k_scatter<<<(e + T - 1) / T, T, 0, s1>>>(src, dst, e);
    k_build_wcat<<<(HID * HID + T - 1) / T, T, 0, s1>>>(Wmu, Wlv);

    // GEMM1 (unscaled) on main stream, overlapped with prep
    k_gemm<INC><<<gblk, 256>>>(x, W1, hs_p, n);

    // join
    cudaEventRecord(evJoin, s1);
    cudaStreamWaitEvent(0, evJoin, 0);

    // fused agg1 + GEMM2, then agg2
    k_fused_agg_gemm<<<gblk, 256, FUSED_SMEM>>>(wcat_p, gs_p, b1, n);
    k_agg2<<<(n * 32 + T - 1) / T, T>>>(bmu, blv, mu, lv, n);
}

// round 8
// speedup vs baseline: 1.0515x; 1.0515x over previous
#include <cuda_runtime.h>
#include <cstdint>

#define NN   100000
#define EE   1600000
#define INC  256
#define HID  128
#define OUTC 64
#define SCAN_B 128
#define MAXBLK 1024
#define NCHUNK 4

// -------- scratch (__device__ globals; allocation is forbidden) --------
static __device__ __align__(256) int   d_degi[NN];
static __device__ __align__(256) int   d_off [NN + 1];
static __device__ __align__(256) int   d_cur [NN];
static __device__ __align__(256) int   d_csr [EE];
static __device__ __align__(256) int   d_bsum [MAXBLK];
static __device__ __align__(256) int   d_bsum2[MAXBLK];
static __device__ __align__(256) float d_dinv[NN];
static __device__ __align__(256) float d_Hs [(size_t)NN * HID];  // x@W1 (unscaled)
static __device__ __align__(256) float d_H1 [(size_t)NN * HID];  // leaky(agg1)
static __device__ __align__(256) float d_Gs [(size_t)NN * HID];  // dinv*(H1@Wcat)
static __device__ __align__(256) float d_Wcat[HID * HID];

// ---------------- packed f32x2 helpers ----------------
static __device__ __forceinline__ void ffma2(unsigned long long& d,
                                             unsigned long long a,
                                             unsigned long long b) {
    asm("fma.rn.f32x2 %0, %1, %2, %0;" : "+l"(d) : "l"(a), "l"(b));
}
static __device__ __forceinline__ unsigned long long bcast2(float f) {
    unsigned long long r;
    asm("mov.b64 %0, {%1, %1};" : "=l"(r) : "f"(f));
    return r;
}

// ---------------- graph preprocessing ----------------
__global__ void k_zero_deg(int n) {
    int i = blockIdx.x * blockDim.x + threadIdx.x;
    if (i < n) d_degi[i] = 0;
}
__global__ void k_degcnt(const int* __restrict__ dst, int e) {
    int i = blockIdx.x * blockDim.x + threadIdx.x;
    if (i < e) atomicAdd(&d_degi[dst[i]], 1);
}
__global__ void k_dinv(int n) {
    int i = blockIdx.x * blockDim.x + threadIdx.x;
    if (i < n) d_dinv[i] = rsqrtf((float)(d_degi[i] + 1));  // +1 self loop
}
__global__ void k_scanA(int n) {
    __shared__ int sm[SCAN_B];
    int b = blockIdx.x, t = threadIdx.x, gi = b * SCAN_B + t;
    int v = (gi < n) ? d_degi[gi] : 0;
    sm[t] = v; __syncthreads();
    #pragma unroll
    for (int s = 1; s < SCAN_B; s <<= 1) {
        int u = (t >= s) ? sm[t - s] : 0;
        __syncthreads(); sm[t] += u; __syncthreads();
    }
    if (gi < n) d_off[gi + 1] = sm[t];
    if (t == SCAN_B - 1) d_bsum[b] = sm[t];
}
__global__ void k_scanB(int nblk) {
    __shared__ int sm[MAXBLK];
    int t = threadIdx.x;
    int v = (t < nblk) ? d_bsum[t] : 0;
    sm[t] = v; __syncthreads();
    #pragma unroll
    for (int s = 1; s < MAXBLK; s <<= 1) {
        int u = (t >= s) ? sm[t - s] : 0;
        __syncthreads(); sm[t] += u; __syncthreads();
    }
    if (t < nblk) d_bsum2[t] = sm[t] - v;
    if (t == 0) d_off[0] = 0;
}
__global__ void k_scanC(int n) {
    int b = blockIdx.x, t = threadIdx.x, gi = b * SCAN_B + t;
    if (gi < n) {
        int o = d_off[gi + 1] + d_bsum2[b];
        d_off[gi + 1] = o;
        d_cur[gi] = o - d_degi[gi];
    }
}
__global__ void k_scatter(const int* __restrict__ src,
                          const int* __restrict__ dst, int e) {
    int i = blockIdx.x * blockDim.x + threadIdx.x;
    if (i < e) {
        int d = dst[i];
        int pos = atomicAdd(&d_cur[d], 1);
        d_csr[pos] = src[i];
    }
}
__global__ void k_build_wcat(const float* __restrict__ Wmu,
                             const float* __restrict__ Wlv) {
    int i = blockIdx.x * blockDim.x + threadIdx.x;
    if (i < HID * HID) {
        int k = i / HID, c = i % HID;
        d_Wcat[i] = (c < OUTC) ? Wmu[k * OUTC + c] : Wlv[k * OUTC + (c - OUTC)];
    }
}

// -------- SGEMM (FFMA2): C[rows,128] = A @ B [* dinv[row]] --------
// BM=128, BN=128, BK=16, 256 threads. row0 = rowbase + blockIdx*128.
template <int K>
__global__ void __launch_bounds__(256)
k_gemm(const float* __restrict__ A, const float* __restrict__ B,
       float* __restrict__ C, const float* __restrict__ dinv,
       int rowbase, int M) {
    constexpr int BM = 128, BN = 128, BK = 16;
    __shared__ float As[BK][BM + 2];
    __shared__ float Bs[BK][BN];

    const int tid = threadIdx.x;
    const int tx  = tid & 15;
    const int ty  = tid >> 4;
    const int row0 = rowbase + blockIdx.x * BM;
    const int arow = tid >> 2;
    const int acol = (tid & 3) * 4;

    unsigned long long acc2[4][8] = {};

    for (int k0 = 0; k0 < K; k0 += BK) {
        #pragma unroll
        for (int i = 0; i < 2; i++) {
            int r  = arow + i * 64;
            int gr = row0 + r;
            float4 av = (gr < M)
                ? *(const float4*)(A + (size_t)gr * K + k0 + acol)
                : make_float4(0.f, 0.f, 0.f, 0.f);
            As[acol + 0][r] = av.x;
            As[acol + 1][r] = av.y;
            As[acol + 2][r] = av.z;
            As[acol + 3][r] = av.w;
        }
        #pragma unroll
        for (int i = 0; i < 2; i++) {
            int idx  = tid + i * 256;
            int brow = idx >> 5;
            int bcol = (idx & 31) * 4;
            *(float4*)&Bs[brow][bcol] =
                *(const float4*)(B + (size_t)(k0 + brow) * BN + bcol);
        }
        __syncthreads();

        #pragma unroll
        for (int kk = 0; kk < BK; kk++) {
            unsigned long long a2[4];
            const unsigned long long* ap =
                (const unsigned long long*)&As[kk][ty * 8];
            #pragma unroll
            for (int j = 0; j < 4; j++) a2[j] = ap[j];
            float bv[8];
            *(float4*)&bv[0] = *(float4*)&Bs[kk][tx * 8];
            *(float4*)&bv[4] = *(float4*)&Bs[kk][tx * 8 + 4];
            unsigned long long b2[8];
            #pragma unroll
            for (int i = 0; i < 8; i++) b2[i] = bcast2(bv[i]);
            #pragma unroll
            for (int j = 0; j < 4; j++)
                #pragma unroll
                for (int i = 0; i < 8; i++)
                    ffma2(acc2[j][i], a2[j], b2[i]);
        }
        __syncthreads();
    }

    #pragma unroll
    for (int j = 0; j < 4; j++) {
        int r0 = row0 + ty * 8 + 2 * j;
        float lo[8], hi[8];
        #pragma unroll
        for (int i = 0; i < 8; i++) {
            lo[i] = __uint_as_float((uint32_t)(acc2[j][i] & 0xffffffffull));
            hi[i] = __uint_as_float((uint32_t)(acc2[j][i] >> 32));
        }
        if (r0 < M) {
            float s = dinv ? dinv[r0] : 1.0f;
            float* cp = C + (size_t)r0 * BN + tx * 8;
            *(float4*)cp       = make_float4(lo[0]*s, lo[1]*s, lo[2]*s, lo[3]*s);
            *(float4*)(cp + 4) = make_float4(lo[4]*s, lo[5]*s, lo[6]*s, lo[7]*s);
        }
        if (r0 + 1 < M) {
            float s = dinv ? dinv[r0 + 1] : 1.0f;
            float* cp = C + (size_t)(r0 + 1) * BN + tx * 8;
            *(float4*)cp       = make_float4(hi[0]*s, hi[1]*s, hi[2]*s, hi[3]*s);
            *(float4*)(cp + 4) = make_float4(hi[4]*s, hi[5]*s, hi[6]*s, hi[7]*s);
        }
    }
}

// -------- agg1: warp per node, range [lo,hi); Hs unscaled --------
// H1[d] = leaky( dinv[d]*( Σ dinv[s]*Hs[s] + dinv[d]*Hs[d] ) + b1 )
__global__ void k_agg1(const float* __restrict__ b1, int lo, int hi) {
    int d = lo + ((blockIdx.x * blockDim.x + threadIdx.x) >> 5);
    int lane = threadIdx.x & 31;
    if (d >= hi) return;
    const float4* base = (const float4*)d_Hs;
    float sd = d_dinv[d];
    float4 acc = base[(size_t)d * 32 + lane];           // self
    acc.x *= sd; acc.y *= sd; acc.z *= sd; acc.w *= sd;
    int beg = d_off[d], end = d_off[d + 1];
    for (int k = beg; k < end; k += 32) {
        int rem = end - k;
        int   s  = (lane < rem) ? d_csr[k + lane] : 0;
        float sv = (lane < rem) ? d_dinv[s] : 0.f;
        int cnt = rem < 32 ? rem : 32;
        for (int j = 0; j < cnt; j++) {
            int   sj = __shfl_sync(0xffffffffu, s,  j);
            float dv = __shfl_sync(0xffffffffu, sv, j);
            float4 v = base[(size_t)sj * 32 + lane];
            acc.x += v.x * dv; acc.y += v.y * dv;
            acc.z += v.z * dv; acc.w += v.w * dv;
        }
    }
    float4 bb = *(const float4*)(b1 + lane * 4);
    float4 r;
    r.x = acc.x * sd + bb.x; r.y = acc.y * sd + bb.y;
    r.z = acc.z * sd + bb.z; r.w = acc.w * sd + bb.w;
    r.x = r.x >= 0.f ? r.x : 0.01f * r.x;
    r.y = r.y >= 0.f ? r.y : 0.01f * r.y;
    r.z = r.z >= 0.f ? r.z : 0.01f * r.z;
    r.w = r.w >= 0.f ? r.w : 0.01f * r.w;
    *(float4*)(d_H1 + (size_t)d * HID + lane * 4) = r;
}

// -------- agg2: warp per node, Gs pre-scaled rows, split mu|lv --------
__global__ void k_agg2(const float* __restrict__ bmu,
                       const float* __restrict__ blv,
                       float* __restrict__ mu, float* __restrict__ lv, int n) {
    int d = (blockIdx.x * blockDim.x + threadIdx.x) >> 5;
    int lane = threadIdx.x & 31;
    if (d >= n) return;
    const float4* base = (const float4*)d_Gs;
    float4 acc = base[(size_t)d * 32 + lane];           // self (pre-scaled)
    int beg = d_off[d], end = d_off[d + 1];
    for (int k = beg; k < end; k += 32) {
        int rem = end - k;
        int s = (lane < rem) ? d_csr[k + lane] : 0;
        int cnt = rem < 32 ? rem : 32;
        for (int j = 0; j < cnt; j++) {
            int sj = __shfl_sync(0xffffffffu, s, j);
            float4 v = base[(size_t)sj * 32 + lane];
            acc.x += v.x; acc.y += v.y; acc.z += v.z; acc.w += v.w;
        }
    }
    float sc = d_dinv[d];
    float4 bb = (lane < 16) ? *(const float4*)(bmu + lane * 4)
                            : *(const float4*)(blv + (lane - 16) * 4);
    float4 r;
    r.x = acc.x * sc + bb.x; r.y = acc.y * sc + bb.y;
    r.z = acc.z * sc + bb.z; r.w = acc.w * sc + bb.w;
    float* p = (lane < 16) ? (mu + (size_t)d * OUTC + lane * 4)
                           : (lv + (size_t)d * OUTC + (lane - 16) * 4);
    *(float4*)p = r;
}

// ---------------- launch ----------------
extern "C" void kernel_launch(void* const* d_in, const int* in_sizes, int n_in,
                              void* d_out, int out_size) {
    const float* x   = (const float*)d_in[0];
    const int*   ei  = (const int*)d_in[1];     // int32 (JAX x64 disabled)
    const float* W1  = (const float*)d_in[2];
    const float* b1  = (const float*)d_in[3];
    const float* Wmu = (const float*)d_in[4];
    const float* bmu = (const float*)d_in[5];
    const float* Wlv = (const float*)d_in[6];
    const float* blv = (const float*)d_in[7];

    const int e = in_sizes[1] / 2;
    const int n = in_sizes[0] / INC;
    const int* src = ei;
    const int* dst = ei + e;

    float* mu = (float*)d_out;
    float* lv = mu + (size_t)n * OUTC;

    float *hs_p, *h1_p, *gs_p, *wcat_p, *dinv_p;
    cudaGetSymbolAddress((void**)&hs_p,   d_Hs);
    cudaGetSymbolAddress((void**)&h1_p,   d_H1);
    cudaGetSymbolAddress((void**)&gs_p,   d_Gs);
    cudaGetSymbolAddress((void**)&wcat_p, d_Wcat);
    cudaGetSymbolAddress((void**)&dinv_p, d_dinv);

    static cudaStream_t s1 = nullptr;
    static cudaEvent_t  evFork = nullptr, evJoin = nullptr, evJoin2 = nullptr;
    static cudaEvent_t  evC[NCHUNK] = {};
    if (!s1) {
        cudaStreamCreateWithFlags(&s1, cudaStreamNonBlocking);
        cudaEventCreateWithFlags(&evFork, cudaEventDisableTiming);
        cudaEventCreateWithFlags(&evJoin, cudaEventDisableTiming);
        cudaEventCreateWithFlags(&evJoin2, cudaEventDisableTiming);
        for (int c = 0; c < NCHUNK; c++)
            cudaEventCreateWithFlags(&evC[c], cudaEventDisableTiming);
    }

    const int T = 256;
    const int nblk = (n + SCAN_B - 1) / SCAN_B;
    const int gblk = (n + 127) / 128;            // 782

    // fork: graph prep on s1 concurrent with GEMM1 on main stream
    cudaEventRecord(evFork, 0);
    cudaStreamWaitEvent(s1, evFork, 0);

    k_zero_deg<<<(n + T - 1) / T, T, 0, s1>>>(n);
    k_degcnt<<<(e + T - 1) / T, T, 0, s1>>>(dst, e);
    k_dinv<<<(n + T - 1) / T, T, 0, s1>>>(n);
    k_scanA<<<nblk, SCAN_B, 0, s1>>>(n);
    k_scanB<<<1, MAXBLK, 0, s1>>>(nblk);
    k_scanC<<<nblk, SCAN_B, 0, s1>>>(n);
    k_scatter<<<(e + T - 1) / T, T, 0, s1>>>(src, dst, e);
    k_build_wcat<<<(HID * HID + T - 1) / T, T, 0, s1>>>(Wmu, Wlv);

    // GEMM1 (unscaled) on main stream, overlapped with prep
    k_gemm<INC><<<gblk, 256>>>(x, W1, hs_p, nullptr, 0, n);

    // join: prep results needed by agg1
    cudaEventRecord(evJoin, s1);
    cudaStreamWaitEvent(0, evJoin, 0);

    // pipelined agg1 (main) -> GEMM2 (s1) over node chunks
    const int ctasPer = (gblk + NCHUNK - 1) / NCHUNK;   // 196
    int ctaDone = 0;
    for (int c = 0; c < NCHUNK; c++) {
        int ctas = (ctaDone + ctasPer <= gblk) ? ctasPer : (gblk - ctaDone);
        if (ctas <= 0) break;
        int lo = ctaDone * 128;
        int hi = lo + ctas * 128; if (hi > n) hi = n;
        int cnt = hi - lo;
        k_agg1<<<(cnt * 32 + T - 1) / T, T>>>(b1, lo, hi);
        cudaEventRecord(evC[c], 0);
        cudaStreamWaitEvent(s1, evC[c], 0);
        k_gemm<HID><<<ctas, 256, 0, s1>>>(h1_p, wcat_p, gs_p, dinv_p, lo, n);
        ctaDone += ctas;
    }

    // join GEMM2 stream, then final aggregation
    cudaEventRecord(evJoin2, s1);
    cudaStreamWaitEvent(0, evJoin2, 0);
    k_agg2<<<(n * 32 + T - 1) / T, T>>>(bmu, blv, mu, lv, n);
}

// round 9
// speedup vs baseline: 1.1335x; 1.0780x over previous
#include <cuda_runtime.h>
#include <cstdint>

#define NN   100000
#define EE   1600000
#define INC  256
#define HID  128
#define OUTC 64
#define SCAN_B 128
#define MAXBLK 1024

// -------- scratch (__device__ globals; allocation is forbidden) --------
static __device__ __align__(256) int   d_degi[NN];
static __device__ __align__(256) int   d_off [NN + 1];
static __device__ __align__(256) int   d_cur [NN];
static __device__ __align__(256) int   d_csr [EE];
static __device__ __align__(256) int   d_bsum [MAXBLK];
static __device__ __align__(256) int   d_bsum2[MAXBLK];
static __device__ __align__(256) float d_dinv[NN];
static __device__ __align__(256) float d_Hs [(size_t)NN * HID];  // x@W1 (unscaled)
static __device__ __align__(256) float d_H1 [(size_t)NN * HID];  // leaky(agg1)
static __device__ __align__(256) float d_Gs [(size_t)NN * HID];  // dinv*(H1@Wcat)
static __device__ __align__(256) float d_Wcat[HID * HID];

// ---------------- packed f32x2 helpers ----------------
static __device__ __forceinline__ void ffma2(unsigned long long& d,
                                             unsigned long long a,
                                             unsigned long long b) {
    asm("fma.rn.f32x2 %0, %1, %2, %0;" : "+l"(d) : "l"(a), "l"(b));
}
static __device__ __forceinline__ unsigned long long bcast2(float f) {
    unsigned long long r;
    asm("mov.b64 %0, {%1, %1};" : "=l"(r) : "f"(f));
    return r;
}

// ---------------- graph preprocessing ----------------
__global__ void k_zero_deg(int n) {
    int i = blockIdx.x * blockDim.x + threadIdx.x;
    if (i < n) d_degi[i] = 0;
}
__global__ void k_degcnt(const int* __restrict__ dst, int e) {
    int i = blockIdx.x * blockDim.x + threadIdx.x;
    if (i < e) atomicAdd(&d_degi[dst[i]], 1);
}
__global__ void k_dinv(int n) {
    int i = blockIdx.x * blockDim.x + threadIdx.x;
    if (i < n) d_dinv[i] = rsqrtf((float)(d_degi[i] + 1));  // +1 self loop
}
__global__ void k_scanA(int n) {
    __shared__ int sm[SCAN_B];
    int b = blockIdx.x, t = threadIdx.x, gi = b * SCAN_B + t;
    int v = (gi < n) ? d_degi[gi] : 0;
    sm[t] = v; __syncthreads();
    #pragma unroll
    for (int s = 1; s < SCAN_B; s <<= 1) {
        int u = (t >= s) ? sm[t - s] : 0;
        __syncthreads(); sm[t] += u; __syncthreads();
    }
    if (gi < n) d_off[gi + 1] = sm[t];
    if (t == SCAN_B - 1) d_bsum[b] = sm[t];
}
__global__ void k_scanB(int nblk) {
    __shared__ int sm[MAXBLK];
    int t = threadIdx.x;
    int v = (t < nblk) ? d_bsum[t] : 0;
    sm[t] = v; __syncthreads();
    #pragma unroll
    for (int s = 1; s < MAXBLK; s <<= 1) {
        int u = (t >= s) ? sm[t - s] : 0;
        __syncthreads(); sm[t] += u; __syncthreads();
    }
    if (t < nblk) d_bsum2[t] = sm[t] - v;
    if (t == 0) d_off[0] = 0;
}
__global__ void k_scanC(int n) {
    int b = blockIdx.x, t = threadIdx.x, gi = b * SCAN_B + t;
    if (gi < n) {
        int o = d_off[gi + 1] + d_bsum2[b];
        d_off[gi + 1] = o;
        d_cur[gi] = o - d_degi[gi];
    }
}
__global__ void k_scatter(const int* __restrict__ src,
                          const int* __restrict__ dst, int e) {
    int i = blockIdx.x * blockDim.x + threadIdx.x;
    if (i < e) {
        int d = dst[i];
        int pos = atomicAdd(&d_cur[d], 1);
        d_csr[pos] = src[i];
    }
}
__global__ void k_build_wcat(const float* __restrict__ Wmu,
                             const float* __restrict__ Wlv) {
    int i = blockIdx.x * blockDim.x + threadIdx.x;
    if (i < HID * HID) {
        int k = i / HID, c = i % HID;
        d_Wcat[i] = (c < OUTC) ? Wmu[k * OUTC + c] : Wlv[k * OUTC + (c - OUTC)];
    }
}

// -------- SGEMM (FFMA2): C[M,128] = A[M,K] @ B[K,128] [* dinv[row]] --------
template <int K>
__global__ void __launch_bounds__(256)
k_gemm(const float* __restrict__ A, const float* __restrict__ B,
       float* __restrict__ C, const float* __restrict__ dinv, int M) {
    constexpr int BM = 128, BN = 128, BK = 16;
    __shared__ float As[BK][BM + 2];
    __shared__ float Bs[BK][BN];

    const int tid = threadIdx.x;
    const int tx  = tid & 15;
    const int ty  = tid >> 4;
    const int row0 = blockIdx.x * BM;
    const int arow = tid >> 2;
    const int acol = (tid & 3) * 4;

    unsigned long long acc2[4][8] = {};

    for (int k0 = 0; k0 < K; k0 += BK) {
        #pragma unroll
        for (int i = 0; i < 2; i++) {
            int r  = arow + i * 64;
            int gr = row0 + r;
            float4 av = (gr < M)
                ? *(const float4*)(A + (size_t)gr * K + k0 + acol)
                : make_float4(0.f, 0.f, 0.f, 0.f);
            As[acol + 0][r] = av.x;
            As[acol + 1][r] = av.y;
            As[acol + 2][r] = av.z;
            As[acol + 3][r] = av.w;
        }
        #pragma unroll
        for (int i = 0; i < 2; i++) {
            int idx  = tid + i * 256;
            int brow = idx >> 5;
            int bcol = (idx & 31) * 4;
            *(float4*)&Bs[brow][bcol] =
                *(const float4*)(B + (size_t)(k0 + brow) * BN + bcol);
        }
        __syncthreads();

        #pragma unroll
        for (int kk = 0; kk < BK; kk++) {
            unsigned long long a2[4];
            const unsigned long long* ap =
                (const unsigned long long*)&As[kk][ty * 8];
            #pragma unroll
            for (int j = 0; j < 4; j++) a2[j] = ap[j];
            float bv[8];
            *(float4*)&bv[0] = *(float4*)&Bs[kk][tx * 8];
            *(float4*)&bv[4] = *(float4*)&Bs[kk][tx * 8 + 4];
            unsigned long long b2[8];
            #pragma unroll
            for (int i = 0; i < 8; i++) b2[i] = bcast2(bv[i]);
            #pragma unroll
            for (int j = 0; j < 4; j++)
                #pragma unroll
                for (int i = 0; i < 8; i++)
                    ffma2(acc2[j][i], a2[j], b2[i]);
        }
        __syncthreads();
    }

    #pragma unroll
    for (int j = 0; j < 4; j++) {
        int r0 = row0 + ty * 8 + 2 * j;
        float lo[8], hi[8];
        #pragma unroll
        for (int i = 0; i < 8; i++) {
            lo[i] = __uint_as_float((uint32_t)(acc2[j][i] & 0xffffffffull));
            hi[i] = __uint_as_float((uint32_t)(acc2[j][i] >> 32));
        }
        if (r0 < M) {
            float s = dinv ? dinv[r0] : 1.0f;
            float* cp = C + (size_t)r0 * BN + tx * 8;
            *(float4*)cp       = make_float4(lo[0]*s, lo[1]*s, lo[2]*s, lo[3]*s);
            *(float4*)(cp + 4) = make_float4(lo[4]*s, lo[5]*s, lo[6]*s, lo[7]*s);
        }
        if (r0 + 1 < M) {
            float s = dinv ? dinv[r0 + 1] : 1.0f;
            float* cp = C + (size_t)(r0 + 1) * BN + tx * 8;
            *(float4*)cp       = make_float4(hi[0]*s, hi[1]*s, hi[2]*s, hi[3]*s);
            *(float4*)(cp + 4) = make_float4(hi[4]*s, hi[5]*s, hi[6]*s, hi[7]*s);
        }
    }
}

// -------- agg1: warp per node, MLP-4 gather; Hs unscaled --------
// H1[d] = leaky( dinv[d]*( Σ dinv[s]*Hs[s] + dinv[d]*Hs[d] ) + b1 )
__global__ void k_agg1(const float* __restrict__ b1, int n) {
    int d = (blockIdx.x * blockDim.x + threadIdx.x) >> 5;
    int lane = threadIdx.x & 31;
    if (d >= n) return;
    const float4* base = (const float4*)d_Hs;
    float sd = d_dinv[d];
    float4 acc = base[(size_t)d * 32 + lane];           // self
    acc.x *= sd; acc.y *= sd; acc.z *= sd; acc.w *= sd;
    int beg = d_off[d], end = d_off[d + 1];
    for (int k = beg; k < end; k += 32) {
        int rem = end - k; if (rem > 32) rem = 32;
        int   s  = (lane < rem) ? d_csr[k + lane] : 0;
        float sv = (lane < rem) ? d_dinv[s] : 0.f;
        int j = 0;
        for (; j + 4 <= rem; j += 4) {
            int s0 = __shfl_sync(0xffffffffu, s, j);
            int s1 = __shfl_sync(0xffffffffu, s, j + 1);
            int s2 = __shfl_sync(0xffffffffu, s, j + 2);
            int s3 = __shfl_sync(0xffffffffu, s, j + 3);
            float d0 = __shfl_sync(0xffffffffu, sv, j);
            float d1 = __shfl_sync(0xffffffffu, sv, j + 1);
            float d2 = __shfl_sync(0xffffffffu, sv, j + 2);
            float d3 = __shfl_sync(0xffffffffu, sv, j + 3);
            float4 v0 = base[(size_t)s0 * 32 + lane];
            float4 v1 = base[(size_t)s1 * 32 + lane];
            float4 v2 = base[(size_t)s2 * 32 + lane];
            float4 v3 = base[(size_t)s3 * 32 + lane];
            acc.x += v0.x * d0 + v1.x * d1 + v2.x * d2 + v3.x * d3;
            acc.y += v0.y * d0 + v1.y * d1 + v2.y * d2 + v3.y * d3;
            acc.z += v0.z * d0 + v1.z * d1 + v2.z * d2 + v3.z * d3;
            acc.w += v0.w * d0 + v1.w * d1 + v2.w * d2 + v3.w * d3;
        }
        for (; j < rem; j++) {
            int   sj = __shfl_sync(0xffffffffu, s,  j);
            float dv = __shfl_sync(0xffffffffu, sv, j);
            float4 v = base[(size_t)sj * 32 + lane];
            acc.x += v.x * dv; acc.y += v.y * dv;
            acc.z += v.z * dv; acc.w += v.w * dv;
        }
    }
    float4 bb = *(const float4*)(b1 + lane * 4);
    float4 r;
    r.x = acc.x * sd + bb.x; r.y = acc.y * sd + bb.y;
    r.z = acc.z * sd + bb.z; r.w = acc.w * sd + bb.w;
    r.x = r.x >= 0.f ? r.x : 0.01f * r.x;
    r.y = r.y >= 0.f ? r.y : 0.01f * r.y;
    r.z = r.z >= 0.f ? r.z : 0.01f * r.z;
    r.w = r.w >= 0.f ? r.w : 0.01f * r.w;
    *(float4*)(d_H1 + (size_t)d * HID + lane * 4) = r;
}

// -------- agg2: warp per node, MLP-4 gather, Gs pre-scaled --------
__global__ void k_agg2(const float* __restrict__ bmu,
                       const float* __restrict__ blv,
                       float* __restrict__ mu, float* __restrict__ lv, int n) {
    int d = (blockIdx.x * blockDim.x + threadIdx.x) >> 5;
    int lane = threadIdx.x & 31;
    if (d >= n) return;
    const float4* base = (const float4*)d_Gs;
    float4 acc = base[(size_t)d * 32 + lane];           // self (pre-scaled)
    int beg = d_off[d], end = d_off[d + 1];
    for (int k = beg; k < end; k += 32) {
        int rem = end - k; if (rem > 32) rem = 32;
        int s = (lane < rem) ? d_csr[k + lane] : 0;
        int j = 0;
        for (; j + 4 <= rem; j += 4) {
            int s0 = __shfl_sync(0xffffffffu, s, j);
            int s1 = __shfl_sync(0xffffffffu, s, j + 1);
            int s2 = __shfl_sync(0xffffffffu, s, j + 2);
            int s3 = __shfl_sync(0xffffffffu, s, j + 3);
            float4 v0 = base[(size_t)s0 * 32 + lane];
            float4 v1 = base[(size_t)s1 * 32 + lane];
            float4 v2 = base[(size_t)s2 * 32 + lane];
            float4 v3 = base[(size_t)s3 * 32 + lane];
            acc.x += v0.x + v1.x + v2.x + v3.x;
            acc.y += v0.y + v1.y + v2.y + v3.y;
            acc.z += v0.z + v1.z + v2.z + v3.z;
            acc.w += v0.w + v1.w + v2.w + v3.w;
        }
        for (; j < rem; j++) {
            int sj = __shfl_sync(0xffffffffu, s, j);
            float4 v = base[(size_t)sj * 32 + lane];
            acc.x += v.x; acc.y += v.y; acc.z += v.z; acc.w += v.w;
        }
    }
    float sc = d_dinv[d];
    float4 bb = (lane < 16) ? *(const float4*)(bmu + lane * 4)
                            : *(const float4*)(blv + (lane - 16) * 4);
    float4 r;
    r.x = acc.x * sc + bb.x; r.y = acc.y * sc + bb.y;
    r.z = acc.z * sc + bb.z; r.w = acc.w * sc + bb.w;
    float* p = (lane < 16) ? (mu + (size_t)d * OUTC + lane * 4)
                           : (lv + (size_t)d * OUTC + (lane - 16) * 4);
    *(float4*)p = r;
}

// ---------------- launch ----------------
extern "C" void kernel_launch(void* const* d_in, const int* in_sizes, int n_in,
                              void* d_out, int out_size) {
    const float* x   = (const float*)d_in[0];
    const int*   ei  = (const int*)d_in[1];     // int32 (JAX x64 disabled)
    const float* W1  = (const float*)d_in[2];
    const float* b1  = (const float*)d_in[3];
    const float* Wmu = (const float*)d_in[4];
    const float* bmu = (const float*)d_in[5];
    const float* Wlv = (const float*)d_in[6];
    const float* blv = (const float*)d_in[7];

    const int e = in_sizes[1] / 2;
    const int n = in_sizes[0] / INC;
    const int* src = ei;
    const int* dst = ei + e;

    float* mu = (float*)d_out;
    float* lv = mu + (size_t)n * OUTC;

    float *hs_p, *h1_p, *gs_p, *wcat_p, *dinv_p;
    cudaGetSymbolAddress((void**)&hs_p,   d_Hs);
    cudaGetSymbolAddress((void**)&h1_p,   d_H1);
    cudaGetSymbolAddress((void**)&gs_p,   d_Gs);
    cudaGetSymbolAddress((void**)&wcat_p, d_Wcat);
    cudaGetSymbolAddress((void**)&dinv_p, d_dinv);

    static cudaStream_t s1 = nullptr;
    static cudaEvent_t  evFork = nullptr, evJoin = nullptr;
    if (!s1) {
        cudaStreamCreateWithFlags(&s1, cudaStreamNonBlocking);
        cudaEventCreateWithFlags(&evFork, cudaEventDisableTiming);
        cudaEventCreateWithFlags(&evJoin, cudaEventDisableTiming);
    }

    const int T = 256;
    const int nblk = (n + SCAN_B - 1) / SCAN_B;
    const int gblk = (n + 127) / 128;

    // fork: graph prep on s1 concurrent with GEMM1 on main stream
    cudaEventRecord(evFork, 0);
    cudaStreamWaitEvent(s1, evFork, 0);

    k_zero_deg<<<(n + T - 1) / T, T, 0, s1>>>(n);
    k_degcnt<<<(e + T - 1) / T, T, 0, s1>>>(dst, e);
    k_dinv<<<(n + T - 1) / T, T, 0, s1>>>(n);
    k_scanA<<<nblk, SCAN_B, 0, s1>>>(n);
    k_scanB<<<1, MAXBLK, 0, s1>>>(nblk);
    k_scanC<<<nblk, SCAN_B, 0, s1>>>(n);
    k_scatter<<<(e + T - 1) / T, T, 0, s1>>>(src, dst, e);
    k_build_wcat<<<(HID * HID + T - 1) / T, T, 0, s1>>>(Wmu, Wlv);

    // GEMM1 (unscaled) on main stream, overlapped with prep
    k_gemm<INC><<<gblk, 256>>>(x, W1, hs_p, nullptr, n);

    // join
    cudaEventRecord(evJoin, s1);
    cudaStreamWaitEvent(0, evJoin, 0);

    // agg1 (folds all dinv scaling), single GEMM2, agg2
    k_agg1<<<(n * 32 + T - 1) / T, T>>>(b1, n);
    k_gemm<HID><<<gblk, 256>>>(h1_p, wcat_p, gs_p, dinv_p, n);
    k_agg2<<<(n * 32 + T - 1) / T, T>>>(bmu, blv, mu, lv, n);
}

// round 10
// speedup vs baseline: 1.1737x; 1.0355x over previous
#include <cuda_runtime.h>
#include <cstdint>

#define NN   100000
#define EE   1600000
#define INC  256
#define HID  128
#define OUTC 64
#define SCAN_B 128
#define MAXBLK 1024

// -------- scratch (__device__ globals; allocation is forbidden) --------
static __device__ __align__(256) int   d_degi[NN];
static __device__ __align__(256) int   d_off [NN + 1];
static __device__ __align__(256) int   d_cur [NN];
static __device__ __align__(256) int   d_csr [EE];
static __device__ __align__(256) int   d_bsum [MAXBLK];
static __device__ __align__(256) int   d_bsum2[MAXBLK];
static __device__ __align__(256) float d_dinv[NN];
static __device__ __align__(256) float d_Hs [(size_t)NN * HID];  // x@W1 (unscaled)
static __device__ __align__(256) float d_H1 [(size_t)NN * HID];  // leaky(agg1)
static __device__ __align__(256) float d_Gs [(size_t)NN * HID];  // dinv*(H1@Wcat)
static __device__ __align__(256) float d_Wcat[HID * HID];

// ---------------- packed f32x2 / async-copy helpers ----------------
static __device__ __forceinline__ void ffma2(unsigned long long& d,
                                             unsigned long long a,
                                             unsigned long long b) {
    asm("fma.rn.f32x2 %0, %1, %2, %0;" : "+l"(d) : "l"(a), "l"(b));
}
static __device__ __forceinline__ unsigned long long bcast2(float f) {
    unsigned long long r;
    asm("mov.b64 %0, {%1, %1};" : "=l"(r) : "f"(f));
    return r;
}
static __device__ __forceinline__ void cp16(void* smem_dst, const void* gsrc) {
    uint32_t s = (uint32_t)__cvta_generic_to_shared(smem_dst);
    asm volatile("cp.async.ca.shared.global [%0], [%1], 16;"
                 :: "r"(s), "l"(gsrc) : "memory");
}
static __device__ __forceinline__ void cp_commit() {
    asm volatile("cp.async.commit_group;" ::: "memory");
}
static __device__ __forceinline__ void cp_wait0() {
    asm volatile("cp.async.wait_group 0;" ::: "memory");
}

// ---------------- graph preprocessing ----------------
__global__ void k_zero_deg(int n) {
    int i = blockIdx.x * blockDim.x + threadIdx.x;
    if (i < n) d_degi[i] = 0;
}
__global__ void k_degcnt(const int* __restrict__ dst, int e) {
    int i = blockIdx.x * blockDim.x + threadIdx.x;
    if (i < e) atomicAdd(&d_degi[dst[i]], 1);
}
__global__ void k_dinv(int n) {
    int i = blockIdx.x * blockDim.x + threadIdx.x;
    if (i < n) d_dinv[i] = rsqrtf((float)(d_degi[i] + 1));  // +1 self loop
}
__global__ void k_scanA(int n) {
    __shared__ int sm[SCAN_B];
    int b = blockIdx.x, t = threadIdx.x, gi = b * SCAN_B + t;
    int v = (gi < n) ? d_degi[gi] : 0;
    sm[t] = v; __syncthreads();
    #pragma unroll
    for (int s = 1; s < SCAN_B; s <<= 1) {
        int u = (t >= s) ? sm[t - s] : 0;
        __syncthreads(); sm[t] += u; __syncthreads();
    }
    if (gi < n) d_off[gi + 1] = sm[t];
    if (t == SCAN_B - 1) d_bsum[b] = sm[t];
}
__global__ void k_scanB(int nblk) {
    __shared__ int sm[MAXBLK];
    int t = threadIdx.x;
    int v = (t < nblk) ? d_bsum[t] : 0;
    sm[t] = v; __syncthreads();
    #pragma unroll
    for (int s = 1; s < MAXBLK; s <<= 1) {
        int u = (t >= s) ? sm[t - s] : 0;
        __syncthreads(); sm[t] += u; __syncthreads();
    }
    if (t < nblk) d_bsum2[t] = sm[t] - v;
    if (t == 0) d_off[0] = 0;
}
__global__ void k_scanC(int n) {
    int b = blockIdx.x, t = threadIdx.x, gi = b * SCAN_B + t;
    if (gi < n) {
        int o = d_off[gi + 1] + d_bsum2[b];
        d_off[gi + 1] = o;
        d_cur[gi] = o - d_degi[gi];
    }
}
__global__ void k_scatter(const int* __restrict__ src,
                          const int* __restrict__ dst, int e) {
    int i = blockIdx.x * blockDim.x + threadIdx.x;
    if (i < e) {
        int d = dst[i];
        int pos = atomicAdd(&d_cur[d], 1);
        d_csr[pos] = src[i];
    }
}
__global__ void k_build_wcat(const float* __restrict__ Wmu,
                             const float* __restrict__ Wlv) {
    int i = blockIdx.x * blockDim.x + threadIdx.x;
    if (i < HID * HID) {
        int k = i / HID, c = i % HID;
        d_Wcat[i] = (c < OUTC) ? Wmu[k * OUTC + c] : Wlv[k * OUTC + (c - OUTC)];
    }
}

// -------- SGEMM (FFMA2, 2-stage cp.async pipeline) --------
// C[M,128] = A[M,K] @ B[K,128] [* dinv[row]]
template <int K>
__global__ void __launch_bounds__(256)
k_gemm(const float* __restrict__ A, const float* __restrict__ B,
       float* __restrict__ C, const float* __restrict__ dinv, int M) {
    constexpr int BM = 128, BN = 128, BK = 16;
    constexpr int NIT = K / BK;
    __shared__ float As[2][BK][BM + 2];
    __shared__ float Bs[2][BK][BN];

    const int tid = threadIdx.x;
    const int tx  = tid & 15;
    const int ty  = tid >> 4;
    const int row0 = blockIdx.x * BM;
    const int arow = tid >> 2;          // 0..63
    const int acol = (tid & 3) * 4;
    const int gr0 = row0 + arow;
    const int gr1 = row0 + arow + 64;

    float4 a0, a1;                      // register-staged A fragments

    auto aload = [&](int it) {
        int k0 = it * BK;
        a0 = (gr0 < M) ? *(const float4*)(A + (size_t)gr0 * K + k0 + acol)
                       : make_float4(0.f, 0.f, 0.f, 0.f);
        a1 = (gr1 < M) ? *(const float4*)(A + (size_t)gr1 * K + k0 + acol)
                       : make_float4(0.f, 0.f, 0.f, 0.f);
    };
    auto asts = [&](int b) {
        As[b][acol + 0][arow] = a0.x;
        As[b][acol + 1][arow] = a0.y;
        As[b][acol + 2][arow] = a0.z;
        As[b][acol + 3][arow] = a0.w;
        As[b][acol + 0][arow + 64] = a1.x;
        As[b][acol + 1][arow + 64] = a1.y;
        As[b][acol + 2][arow + 64] = a1.z;
        As[b][acol + 3][arow + 64] = a1.w;
    };
    auto bload = [&](int it, int b) {
        #pragma unroll
        for (int i = 0; i < 2; i++) {
            int idx  = tid + i * 256;
            int brow = idx >> 5;
            int bcol = (idx & 31) * 4;
            cp16(&Bs[b][brow][bcol],
                 B + (size_t)(it * BK + brow) * BN + bcol);
        }
        cp_commit();
    };

    unsigned long long acc2[4][8] = {};

    // prologue: stage 0
    aload(0);
    bload(0, 0);
    asts(0);
    cp_wait0();
    __syncthreads();

    int buf = 0;
    for (int it = 0; it < NIT; it++) {
        if (it + 1 < NIT) {
            aload(it + 1);          // LDG in flight during compute
            bload(it + 1, buf ^ 1); // cp.async in flight during compute
        }
        #pragma unroll
        for (int kk = 0; kk < BK; kk++) {
            unsigned long long a2[4];
            const unsigned long long* ap =
                (const unsigned long long*)&As[buf][kk][ty * 8];
            #pragma unroll
            for (int j = 0; j < 4; j++) a2[j] = ap[j];
            float bv[8];
            *(float4*)&bv[0] = *(float4*)&Bs[buf][kk][tx * 8];
            *(float4*)&bv[4] = *(float4*)&Bs[buf][kk][tx * 8 + 4];
            unsigned long long b2[8];
            #pragma unroll
            for (int i = 0; i < 8; i++) b2[i] = bcast2(bv[i]);
            #pragma unroll
            for (int j = 0; j < 4; j++)
                #pragma unroll
                for (int i = 0; i < 8; i++)
                    ffma2(acc2[j][i], a2[j], b2[i]);
        }
        if (it + 1 < NIT) {
            asts(buf ^ 1);          // stalls only on the A LDG scoreboard
            cp_wait0();             // B tile landed
        }
        __syncthreads();
        buf ^= 1;
    }

    #pragma unroll
    for (int j = 0; j < 4; j++) {
        int r0 = row0 + ty * 8 + 2 * j;
        float lo[8], hi[8];
        #pragma unroll
        for (int i = 0; i < 8; i++) {
            lo[i] = __uint_as_float((uint32_t)(acc2[j][i] & 0xffffffffull));
            hi[i] = __uint_as_float((uint32_t)(acc2[j][i] >> 32));
        }
        if (r0 < M) {
            float s = dinv ? dinv[r0] : 1.0f;
            float* cp = C + (size_t)r0 * BN + tx * 8;
            *(float4*)cp       = make_float4(lo[0]*s, lo[1]*s, lo[2]*s, lo[3]*s);
            *(float4*)(cp + 4) = make_float4(lo[4]*s, lo[5]*s, lo[6]*s, lo[7]*s);
        }
        if (r0 + 1 < M) {
            float s = dinv ? dinv[r0 + 1] : 1.0f;
            float* cp = C + (size_t)(r0 + 1) * BN + tx * 8;
            *(float4*)cp       = make_float4(hi[0]*s, hi[1]*s, hi[2]*s, hi[3]*s);
            *(float4*)(cp + 4) = make_float4(hi[4]*s, hi[5]*s, hi[6]*s, hi[7]*s);
        }
    }
}

// -------- agg1: warp per node, MLP-4 gather; Hs unscaled --------
__global__ void k_agg1(const float* __restrict__ b1, int n) {
    int d = (blockIdx.x * blockDim.x + threadIdx.x) >> 5;
    int lane = threadIdx.x & 31;
    if (d >= n) return;
    const float4* base = (const float4*)d_Hs;
    float sd = d_dinv[d];
    float4 acc = base[(size_t)d * 32 + lane];           // self
    acc.x *= sd; acc.y *= sd; acc.z *= sd; acc.w *= sd;
    int beg = d_off[d], end = d_off[d + 1];
    for (int k = beg; k < end; k += 32) {
        int rem = end - k; if (rem > 32) rem = 32;
        int   s  = (lane < rem) ? d_csr[k + lane] : 0;
        float sv = (lane < rem) ? d_dinv[s] : 0.f;
        int j = 0;
        for (; j + 4 <= rem; j += 4) {
            int s0 = __shfl_sync(0xffffffffu, s, j);
            int s1 = __shfl_sync(0xffffffffu, s, j + 1);
            int s2 = __shfl_sync(0xffffffffu, s, j + 2);
            int s3 = __shfl_sync(0xffffffffu, s, j + 3);
            float d0 = __shfl_sync(0xffffffffu, sv, j);
            float d1 = __shfl_sync(0xffffffffu, sv, j + 1);
            float d2 = __shfl_sync(0xffffffffu, sv, j + 2);
            float d3 = __shfl_sync(0xffffffffu, sv, j + 3);
            float4 v0 = base[(size_t)s0 * 32 + lane];
            float4 v1 = base[(size_t)s1 * 32 + lane];
            float4 v2 = base[(size_t)s2 * 32 + lane];
            float4 v3 = base[(size_t)s3 * 32 + lane];
            acc.x += v0.x * d0 + v1.x * d1 + v2.x * d2 + v3.x * d3;
            acc.y += v0.y * d0 + v1.y * d1 + v2.y * d2 + v3.y * d3;
            acc.z += v0.z * d0 + v1.z * d1 + v2.z * d2 + v3.z * d3;
            acc.w += v0.w * d0 + v1.w * d1 + v2.w * d2 + v3.w * d3;
        }
        for (; j < rem; j++) {
            int   sj = __shfl_sync(0xffffffffu, s,  j);
            float dv = __shfl_sync(0xffffffffu, sv, j);
            float4 v = base[(size_t)sj * 32 + lane];
            acc.x += v.x * dv; acc.y += v.y * dv;
            acc.z += v.z * dv; acc.w += v.w * dv;
        }
    }
    float4 bb = *(const float4*)(b1 + lane * 4);
    float4 r;
    r.x = acc.x * sd + bb.x; r.y = acc.y * sd + bb.y;
    r.z = acc.z * sd + bb.z; r.w = acc.w * sd + bb.w;
    r.x = r.x >= 0.f ? r.x : 0.01f * r.x;
    r.y = r.y >= 0.f ? r.y : 0.01f * r.y;
    r.z = r.z >= 0.f ? r.z : 0.01f * r.z;
    r.w = r.w >= 0.f ? r.w : 0.01f * r.w;
    *(float4*)(d_H1 + (size_t)d * HID + lane * 4) = r;
}

// -------- agg2: warp per node, MLP-4 gather, Gs pre-scaled --------
__global__ void k_agg2(const float* __restrict__ bmu,
                       const float* __restrict__ blv,
                       float* __restrict__ mu, float* __restrict__ lv, int n) {
    int d = (blockIdx.x * blockDim.x + threadIdx.x) >> 5;
    int lane = threadIdx.x & 31;
    if (d >= n) return;
    const float4* base = (const float4*)d_Gs;
    float4 acc = base[(size_t)d * 32 + lane];           // self (pre-scaled)
    int beg = d_off[d], end = d_off[d + 1];
    for (int k = beg; k < end; k += 32) {
        int rem = end - k; if (rem > 32) rem = 32;
        int s = (lane < rem) ? d_csr[k + lane] : 0;
        int j = 0;
        for (; j + 4 <= rem; j += 4) {
            int s0 = __shfl_sync(0xffffffffu, s, j);
            int s1 = __shfl_sync(0xffffffffu, s, j + 1);
            int s2 = __shfl_sync(0xffffffffu, s, j + 2);
            int s3 = __shfl_sync(0xffffffffu, s, j + 3);
            float4 v0 = base[(size_t)s0 * 32 + lane];
            float4 v1 = base[(size_t)s1 * 32 + lane];
            float4 v2 = base[(size_t)s2 * 32 + lane];
            float4 v3 = base[(size_t)s3 * 32 + lane];
            acc.x += v0.x + v1.x + v2.x + v3.x;
            acc.y += v0.y + v1.y + v2.y + v3.y;
            acc.z += v0.z + v1.z + v2.z + v3.z;
            acc.w += v0.w + v1.w + v2.w + v3.w;
        }
        for (; j < rem; j++) {
            int sj = __shfl_sync(0xffffffffu, s, j);
            float4 v = base[(size_t)sj * 32 + lane];
            acc.x += v.x; acc.y += v.y; acc.z += v.z; acc.w += v.w;
        }
    }
    float sc = d_dinv[d];
    float4 bb = (lane < 16) ? *(const float4*)(bmu + lane * 4)
                            : *(const float4*)(blv + (lane - 16) * 4);
    float4 r;
    r.x = acc.x * sc + bb.x; r.y = acc.y * sc + bb.y;
    r.z = acc.z * sc + bb.z; r.w = acc.w * sc + bb.w;
    float* p = (lane < 16) ? (mu + (size_t)d * OUTC + lane * 4)
                           : (lv + (size_t)d * OUTC + (lane - 16) * 4);
    *(float4*)p = r;
}

// ---------------- launch ----------------
extern "C" void kernel_launch(void* const* d_in, const int* in_sizes, int n_in,
                              void* d_out, int out_size) {
    const float* x   = (const float*)d_in[0];
    const int*   ei  = (const int*)d_in[1];     // int32 (JAX x64 disabled)
    const float* W1  = (const float*)d_in[2];
    const float* b1  = (const float*)d_in[3];
    const float* Wmu = (const float*)d_in[4];
    const float* bmu = (const float*)d_in[5];
    const float* Wlv = (const float*)d_in[6];
    const float* blv = (const float*)d_in[7];

    const int e = in_sizes[1] / 2;
    const int n = in_sizes[0] / INC;
    const int* src = ei;
    const int* dst = ei + e;

    float* mu = (float*)d_out;
    float* lv = mu + (size_t)n * OUTC;

    float *hs_p, *h1_p, *gs_p, *wcat_p, *dinv_p;
    cudaGetSymbolAddress((void**)&hs_p,   d_Hs);
    cudaGetSymbolAddress((void**)&h1_p,   d_H1);
    cudaGetSymbolAddress((void**)&gs_p,   d_Gs);
    cudaGetSymbolAddress((void**)&wcat_p, d_Wcat);
    cudaGetSymbolAddress((void**)&dinv_p, d_dinv);

    static cudaStream_t s1 = nullptr;
    static cudaEvent_t  evFork = nullptr, evJoin = nullptr;
    if (!s1) {
        cudaStreamCreateWithFlags(&s1, cudaStreamNonBlocking);
        cudaEventCreateWithFlags(&evFork, cudaEventDisableTiming);
        cudaEventCreateWithFlags(&evJoin, cudaEventDisableTiming);
    }

    const int T = 256;
    const int nblk = (n + SCAN_B - 1) / SCAN_B;
    const int gblk = (n + 127) / 128;

    // fork: graph prep on s1 concurrent with GEMM1 on main stream.
    // Submission order puts GEMM1 at launch slot 4 so ncu captures it.
    cudaEventRecord(evFork, 0);
    cudaStreamWaitEvent(s1, evFork, 0);

    k_zero_deg<<<(n + T - 1) / T, T, 0, s1>>>(n);
    k_degcnt<<<(e + T - 1) / T, T, 0, s1>>>(dst, e);
    k_dinv<<<(n + T - 1) / T, T, 0, s1>>>(n);

    // GEMM1 (unscaled) on main stream — 4th launch (profiled)
    k_gemm<INC><<<gblk, 256>>>(x, W1, hs_p, nullptr, n);

    k_scanA<<<nblk, SCAN_B, 0, s1>>>(n);
    k_scanB<<<1, MAXBLK, 0, s1>>>(nblk);
    k_scanC<<<nblk, SCAN_B, 0, s1>>>(n);
    k_scatter<<<(e + T - 1) / T, T, 0, s1>>>(src, dst, e);
    k_build_wcat<<<(HID * HID + T - 1) / T, T, 0, s1>>>(Wmu, Wlv);

    // join
    cudaEventRecord(evJoin, s1);
    cudaStreamWaitEvent(0, evJoin, 0);

    // agg1 (folds all dinv scaling), single GEMM2, agg2
    k_agg1<<<(n * 32 + T - 1) / T, T>>>(b1, n);
    k_gemm<HID><<<gblk, 256>>>(h1_p, wcat_p, gs_p, dinv_p, n);
    k_agg2<<<(n * 32 + T - 1) / T, T>>>(bmu, blv, mu, lv, n);
}

// round 11
// speedup vs baseline: 1.7338x; 1.4772x over previous
#include <cuda_runtime.h>
#include <cstdint>

#define NN   100000
#define EE   1600000
#define INC  256
#define HID  128
#define OUTC 64
#define SCAN_B 128
#define MAXBLK 1024

// -------- scratch (__device__ globals; allocation is forbidden) --------
static __device__ __align__(256) int   d_degi[NN];
static __device__ __align__(256) int   d_off [NN + 1];
static __device__ __align__(256) int   d_cur [NN];
static __device__ __align__(256) int   d_csr [EE];
static __device__ __align__(256) int   d_bsum [MAXBLK];
static __device__ __align__(256) int   d_bsum2[MAXBLK];
static __device__ __align__(256) float d_dinv[NN];
static __device__ __align__(256) float d_Hs [(size_t)NN * HID];  // x@W1 (unscaled)
static __device__ __align__(256) float d_H1 [(size_t)NN * HID];  // leaky(agg1)
static __device__ __align__(256) float d_Gs [(size_t)NN * HID];  // dinv*(H1@Wcat)
static __device__ __align__(256) float d_Wcat[HID * HID];

// ---------------- tf32 helpers ----------------
static __device__ __forceinline__ uint32_t f2tf32(float f) {
    uint32_t r;
    asm("cvt.rna.tf32.f32 %0, %1;" : "=r"(r) : "f"(f));
    return r;
}
static __device__ __forceinline__ void mma_tf32_16x8x8(
    float& c0, float& c1, float& c2, float& c3,
    uint32_t a0, uint32_t a1, uint32_t a2, uint32_t a3,
    uint32_t b0, uint32_t b1) {
    asm volatile(
        "mma.sync.aligned.m16n8k8.row.col.f32.tf32.tf32.f32 "
        "{%0,%1,%2,%3}, {%4,%5,%6,%7}, {%8,%9}, {%0,%1,%2,%3};"
        : "+f"(c0), "+f"(c1), "+f"(c2), "+f"(c3)
        : "r"(a0), "r"(a1), "r"(a2), "r"(a3), "r"(b0), "r"(b1));
}

// ---------------- graph preprocessing ----------------
__global__ void k_zero_deg(int n) {
    int i = blockIdx.x * blockDim.x + threadIdx.x;
    if (i < n) d_degi[i] = 0;
}
__global__ void k_degcnt(const int* __restrict__ dst, int e) {
    int i = blockIdx.x * blockDim.x + threadIdx.x;
    if (i < e) atomicAdd(&d_degi[dst[i]], 1);
}
__global__ void k_dinv(int n) {
    int i = blockIdx.x * blockDim.x + threadIdx.x;
    if (i < n) d_dinv[i] = rsqrtf((float)(d_degi[i] + 1));  // +1 self loop
}
__global__ void k_scanA(int n) {
    __shared__ int sm[SCAN_B];
    int b = blockIdx.x, t = threadIdx.x, gi = b * SCAN_B + t;
    int v = (gi < n) ? d_degi[gi] : 0;
    sm[t] = v; __syncthreads();
    #pragma unroll
    for (int s = 1; s < SCAN_B; s <<= 1) {
        int u = (t >= s) ? sm[t - s] : 0;
        __syncthreads(); sm[t] += u; __syncthreads();
    }
    if (gi < n) d_off[gi + 1] = sm[t];
    if (t == SCAN_B - 1) d_bsum[b] = sm[t];
}
__global__ void k_scanB(int nblk) {
    __shared__ int sm[MAXBLK];
    int t = threadIdx.x;
    int v = (t < nblk) ? d_bsum[t] : 0;
    sm[t] = v; __syncthreads();
    #pragma unroll
    for (int s = 1; s < MAXBLK; s <<= 1) {
        int u = (t >= s) ? sm[t - s] : 0;
        __syncthreads(); sm[t] += u; __syncthreads();
    }
    if (t < nblk) d_bsum2[t] = sm[t] - v;
    if (t == 0) d_off[0] = 0;
}
__global__ void k_scanC(int n) {
    int b = blockIdx.x, t = threadIdx.x, gi = b * SCAN_B + t;
    if (gi < n) {
        int o = d_off[gi + 1] + d_bsum2[b];
        d_off[gi + 1] = o;
        d_cur[gi] = o - d_degi[gi];
    }
}
__global__ void k_scatter(const int* __restrict__ src,
                          const int* __restrict__ dst, int e) {
    int i = blockIdx.x * blockDim.x + threadIdx.x;
    if (i < e) {
        int d = dst[i];
        int pos = atomicAdd(&d_cur[d], 1);
        d_csr[pos] = src[i];
    }
}
__global__ void k_build_wcat(const float* __restrict__ Wmu,
                             const float* __restrict__ Wlv) {
    int i = blockIdx.x * blockDim.x + threadIdx.x;
    if (i < HID * HID) {
        int k = i / HID, c = i % HID;
        d_Wcat[i] = (c < OUTC) ? Wmu[k * OUTC + c] : Wlv[k * OUTC + (c - OUTC)];
    }
}

// -------- tf32 tensor-core GEMM: C[M,128] = A[M,K] @ B[K,128] [*dinv] --------
// 256 thr = 8 warps (2M x 4N), warp tile 64x32 = 4x4 m16n8k8 atoms, BK=16.
// smem strides 20 (A) / 136 (B) -> conflict-free fragment LDS.
template <int K>
__global__ void __launch_bounds__(256)
k_gemm(const float* __restrict__ A, const float* __restrict__ B,
       float* __restrict__ C, const float* __restrict__ dinv, int M) {
    constexpr int BM = 128, BN = 128, BK = 16;
    constexpr int NIT = K / BK;
    constexpr int ASTR = 20, BSTR = 136;
    __shared__ uint32_t sA[2][BM * ASTR];
    __shared__ uint32_t sB[2][BK * BSTR];

    const int tid  = threadIdx.x;
    const int lane = tid & 31;
    const int wid  = tid >> 5;
    const int wm   = wid & 1;          // 0..1 -> M offset wm*64
    const int wn   = wid >> 1;         // 0..3 -> N offset wn*32
    const int gid  = lane >> 2;        // 0..7
    const int tq   = lane & 3;         // 0..3
    const int row0 = blockIdx.x * BM;

    // staging indices: A tile 128x16 (2 float4/thread), B tile 16x128 (2/thread)
    const int ar0 = (tid + 0)   >> 2, ac0 = ((tid + 0)   & 3) * 4;
    const int ar1 = (tid + 256) >> 2, ac1 = ((tid + 256) & 3) * 4;
    const int br0 = (tid + 0)   >> 5, bc0 = ((tid + 0)   & 31) * 4;
    const int br1 = (tid + 256) >> 5, bc1 = ((tid + 256) & 31) * 4;

    float4 av0, av1, bv0, bv1;
    auto gload = [&](int it) {
        int k0 = it * BK;
        int g0 = row0 + ar0, g1 = row0 + ar1;
        av0 = (g0 < M) ? *(const float4*)(A + (size_t)g0 * K + k0 + ac0)
                       : make_float4(0.f, 0.f, 0.f, 0.f);
        av1 = (g1 < M) ? *(const float4*)(A + (size_t)g1 * K + k0 + ac1)
                       : make_float4(0.f, 0.f, 0.f, 0.f);
        bv0 = *(const float4*)(B + (size_t)(k0 + br0) * BN + bc0);
        bv1 = *(const float4*)(B + (size_t)(k0 + br1) * BN + bc1);
    };
    auto sts = [&](int b) {
        uint4 t0 = make_uint4(f2tf32(av0.x), f2tf32(av0.y), f2tf32(av0.z), f2tf32(av0.w));
        uint4 t1 = make_uint4(f2tf32(av1.x), f2tf32(av1.y), f2tf32(av1.z), f2tf32(av1.w));
        *(uint4*)&sA[b][ar0 * ASTR + ac0] = t0;
        *(uint4*)&sA[b][ar1 * ASTR + ac1] = t1;
        uint4 u0 = make_uint4(f2tf32(bv0.x), f2tf32(bv0.y), f2tf32(bv0.z), f2tf32(bv0.w));
        uint4 u1 = make_uint4(f2tf32(bv1.x), f2tf32(bv1.y), f2tf32(bv1.z), f2tf32(bv1.w));
        *(uint4*)&sB[b][br0 * BSTR + bc0] = u0;
        *(uint4*)&sB[b][br1 * BSTR + bc1] = u1;
    };

    float acc[4][4][4] = {};

    gload(0);
    sts(0);
    __syncthreads();

    int buf = 0;
    for (int it = 0; it < NIT; it++) {
        if (it + 1 < NIT) gload(it + 1);    // LDG in flight during MMA
        #pragma unroll
        for (int ks = 0; ks < 2; ks++) {
            const int kk = ks * 8;
            uint32_t af[4][4], bf[4][2];
            #pragma unroll
            for (int mt = 0; mt < 4; mt++) {
                int m = wm * 64 + mt * 16 + gid;
                const uint32_t* pa = &sA[buf][0];
                af[mt][0] = pa[(m    ) * ASTR + kk + tq];
                af[mt][1] = pa[(m + 8) * ASTR + kk + tq];
                af[mt][2] = pa[(m    ) * ASTR + kk + tq + 4];
                af[mt][3] = pa[(m + 8) * ASTR + kk + tq + 4];
            }
            #pragma unroll
            for (int nt = 0; nt < 4; nt++) {
                int nn = wn * 32 + nt * 8 + gid;
                const uint32_t* pb = &sB[buf][0];
                bf[nt][0] = pb[(kk + tq    ) * BSTR + nn];
                bf[nt][1] = pb[(kk + tq + 4) * BSTR + nn];
            }
            #pragma unroll
            for (int mt = 0; mt < 4; mt++)
                #pragma unroll
                for (int nt = 0; nt < 4; nt++)
                    mma_tf32_16x8x8(acc[mt][nt][0], acc[mt][nt][1],
                                    acc[mt][nt][2], acc[mt][nt][3],
                                    af[mt][0], af[mt][1], af[mt][2], af[mt][3],
                                    bf[nt][0], bf[nt][1]);
        }
        if (it + 1 < NIT) sts(buf ^ 1);
        __syncthreads();
        buf ^= 1;
    }

    // epilogue: c0,c1 -> (row, col..col+1); c2,c3 -> (row+8, ...)
    #pragma unroll
    for (int mt = 0; mt < 4; mt++) {
        int ra = row0 + wm * 64 + mt * 16 + gid;
        int rb = ra + 8;
        #pragma unroll
        for (int nt = 0; nt < 4; nt++) {
            int col = wn * 32 + nt * 8 + 2 * tq;
            if (ra < M) {
                float s = dinv ? dinv[ra] : 1.0f;
                *(float2*)(C + (size_t)ra * BN + col) =
                    make_float2(acc[mt][nt][0] * s, acc[mt][nt][1] * s);
            }
            if (rb < M) {
                float s = dinv ? dinv[rb] : 1.0f;
                *(float2*)(C + (size_t)rb * BN + col) =
                    make_float2(acc[mt][nt][2] * s, acc[mt][nt][3] * s);
            }
        }
    }
}

// -------- agg1: warp per node, MLP-4 gather; Hs unscaled --------
__global__ void k_agg1(const float* __restrict__ b1, int n) {
    int d = (blockIdx.x * blockDim.x + threadIdx.x) >> 5;
    int lane = threadIdx.x & 31;
    if (d >= n) return;
    const float4* base = (const float4*)d_Hs;
    float sd = d_dinv[d];
    float4 acc = base[(size_t)d * 32 + lane];           // self
    acc.x *= sd; acc.y *= sd; acc.z *= sd; acc.w *= sd;
    int beg = d_off[d], end = d_off[d + 1];
    for (int k = beg; k < end; k += 32) {
        int rem = end - k; if (rem > 32) rem = 32;
        int   s  = (lane < rem) ? d_csr[k + lane] : 0;
        float sv = (lane < rem) ? d_dinv[s] : 0.f;
        int j = 0;
        for (; j + 4 <= rem; j += 4) {
            int s0 = __shfl_sync(0xffffffffu, s, j);
            int s1 = __shfl_sync(0xffffffffu, s, j + 1);
            int s2 = __shfl_sync(0xffffffffu, s, j + 2);
            int s3 = __shfl_sync(0xffffffffu, s, j + 3);
            float d0 = __shfl_sync(0xffffffffu, sv, j);
            float d1 = __shfl_sync(0xffffffffu, sv, j + 1);
            float d2 = __shfl_sync(0xffffffffu, sv, j + 2);
            float d3 = __shfl_sync(0xffffffffu, sv, j + 3);
            float4 v0 = base[(size_t)s0 * 32 + lane];
            float4 v1 = base[(size_t)s1 * 32 + lane];
            float4 v2 = base[(size_t)s2 * 32 + lane];
            float4 v3 = base[(size_t)s3 * 32 + lane];
            acc.x += v0.x * d0 + v1.x * d1 + v2.x * d2 + v3.x * d3;
            acc.y += v0.y * d0 + v1.y * d1 + v2.y * d2 + v3.y * d3;
            acc.z += v0.z * d0 + v1.z * d1 + v2.z * d2 + v3.z * d3;
            acc.w += v0.w * d0 + v1.w * d1 + v2.w * d2 + v3.w * d3;
        }
        for (; j < rem; j++) {
            int   sj = __shfl_sync(0xffffffffu, s,  j);
            float dv = __shfl_sync(0xffffffffu, sv, j);
            float4 v = base[(size_t)sj * 32 + lane];
            acc.x += v.x * dv; acc.y += v.y * dv;
            acc.z += v.z * dv; acc.w += v.w * dv;
        }
    }
    float4 bb = *(const float4*)(b1 + lane * 4);
    float4 r;
    r.x = acc.x * sd + bb.x; r.y = acc.y * sd + bb.y;
    r.z = acc.z * sd + bb.z; r.w = acc.w * sd + bb.w;
    r.x = r.x >= 0.f ? r.x : 0.01f * r.x;
    r.y = r.y >= 0.f ? r.y : 0.01f * r.y;
    r.z = r.z >= 0.f ? r.z : 0.01f * r.z;
    r.w = r.w >= 0.f ? r.w : 0.01f * r.w;
    *(float4*)(d_H1 + (size_t)d * HID + lane * 4) = r;
}

// -------- agg2: warp per node, MLP-4 gather, Gs pre-scaled --------
__global__ void k_agg2(const float* __restrict__ bmu,
                       const float* __restrict__ blv,
                       float* __restrict__ mu, float* __restrict__ lv, int n) {
    int d = (blockIdx.x * blockDim.x + threadIdx.x) >> 5;
    int lane = threadIdx.x & 31;
    if (d >= n) return;
    const float4* base = (const float4*)d_Gs;
    float4 acc = base[(size_t)d * 32 + lane];           // self (pre-scaled)
    int beg = d_off[d], end = d_off[d + 1];
    for (int k = beg; k < end; k += 32) {
        int rem = end - k; if (rem > 32) rem = 32;
        int s = (lane < rem) ? d_csr[k + lane] : 0;
        int j = 0;
        for (; j + 4 <= rem; j += 4) {
            int s0 = __shfl_sync(0xffffffffu, s, j);
            int s1 = __shfl_sync(0xffffffffu, s, j + 1);
            int s2 = __shfl_sync(0xffffffffu, s, j + 2);
            int s3 = __shfl_sync(0xffffffffu, s, j + 3);
            float4 v0 = base[(size_t)s0 * 32 + lane];
            float4 v1 = base[(size_t)s1 * 32 + lane];
            float4 v2 = base[(size_t)s2 * 32 + lane];
            float4 v3 = base[(size_t)s3 * 32 + lane];
            acc.x += v0.x + v1.x + v2.x + v3.x;
            acc.y += v0.y + v1.y + v2.y + v3.y;
            acc.z += v0.z + v1.z + v2.z + v3.z;
            acc.w += v0.w + v1.w + v2.w + v3.w;
        }
        for (; j < rem; j++) {
            int sj = __shfl_sync(0xffffffffu, s, j);
            float4 v = base[(size_t)sj * 32 + lane];
            acc.x += v.x; acc.y += v.y; acc.z += v.z; acc.w += v.w;
        }
    }
    float sc = d_dinv[d];
    float4 bb = (lane < 16) ? *(const float4*)(bmu + lane * 4)
                            : *(const float4*)(blv + (lane - 16) * 4);
    float4 r;
    r.x = acc.x * sc + bb.x; r.y = acc.y * sc + bb.y;
    r.z = acc.z * sc + bb.z; r.w = acc.w * sc + bb.w;
    float* p = (lane < 16) ? (mu + (size_t)d * OUTC + lane * 4)
                           : (lv + (size_t)d * OUTC + (lane - 16) * 4);
    *(float4*)p = r;
}

// ---------------- launch ----------------
extern "C" void kernel_launch(void* const* d_in, const int* in_sizes, int n_in,
                              void* d_out, int out_size) {
    const float* x   = (const float*)d_in[0];
    const int*   ei  = (const int*)d_in[1];     // int32 (JAX x64 disabled)
    const float* W1  = (const float*)d_in[2];
    const float* b1  = (const float*)d_in[3];
    const float* Wmu = (const float*)d_in[4];
    const float* bmu = (const float*)d_in[5];
    const float* Wlv = (const float*)d_in[6];
    const float* blv = (const float*)d_in[7];

    const int e = in_sizes[1] / 2;
    const int n = in_sizes[0] / INC;
    const int* src = ei;
    const int* dst = ei + e;

    float* mu = (float*)d_out;
    float* lv = mu + (size_t)n * OUTC;

    float *hs_p, *h1_p, *gs_p, *wcat_p, *dinv_p;
    cudaGetSymbolAddress((void**)&hs_p,   d_Hs);
    cudaGetSymbolAddress((void**)&h1_p,   d_H1);
    cudaGetSymbolAddress((void**)&gs_p,   d_Gs);
    cudaGetSymbolAddress((void**)&wcat_p, d_Wcat);
    cudaGetSymbolAddress((void**)&dinv_p, d_dinv);

    static cudaStream_t s1 = nullptr;
    static cudaEvent_t  evFork = nullptr, evJoin = nullptr;
    if (!s1) {
        cudaStreamCreateWithFlags(&s1, cudaStreamNonBlocking);
        cudaEventCreateWithFlags(&evFork, cudaEventDisableTiming);
        cudaEventCreateWithFlags(&evJoin, cudaEventDisableTiming);
    }

    const int T = 256;
    const int nblk = (n + SCAN_B - 1) / SCAN_B;
    const int gblk = (n + 127) / 128;

    // fork: graph prep on s1 concurrent with GEMM1 on main stream.
    // GEMM1 stays at launch slot 4 so ncu captures it.
    cudaEventRecord(evFork, 0);
    cudaStreamWaitEvent(s1, evFork, 0);

    k_zero_deg<<<(n + T - 1) / T, T, 0, s1>>>(n);
    k_degcnt<<<(e + T - 1) / T, T, 0, s1>>>(dst, e);
    k_dinv<<<(n + T - 1) / T, T, 0, s1>>>(n);

    // GEMM1 (tf32 tensor cores, unscaled) — 4th launch (profiled)
    k_gemm<INC><<<gblk, 256>>>(x, W1, hs_p, nullptr, n);

    k_scanA<<<nblk, SCAN_B, 0, s1>>>(n);
    k_scanB<<<1, MAXBLK, 0, s1>>>(nblk);
    k_scanC<<<nblk, SCAN_B, 0, s1>>>(n);
    k_scatter<<<(e + T - 1) / T, T, 0, s1>>>(src, dst, e);
    k_build_wcat<<<(HID * HID + T - 1) / T, T, 0, s1>>>(Wmu, Wlv);

    // join
    cudaEventRecord(evJoin, s1);
    cudaStreamWaitEvent(0, evJoin, 0);

    // agg1 (folds all dinv scaling), GEMM2 (tf32), agg2
    k_agg1<<<(n * 32 + T - 1) / T, T>>>(b1, n);
    k_gemm<HID><<<gblk, 256>>>(h1_p, wcat_p, gs_p, dinv_p, n);
    k_agg2<<<(n * 32 + T - 1) / T, T>>>(bmu, blv, mu, lv, n);
}

// round 12
// speedup vs baseline: 1.7955x; 1.0356x over previous
#include <cuda_runtime.h>
#include <cstdint>

#define NN   100000
#define EE   1600000
#define INC  256
#define HID  128
#define OUTC 64
#define SCAN_B 128
#define MAXBLK 1024

// -------- scratch (__device__ globals; allocation is forbidden) --------
static __device__ __align__(256) int   d_degi[NN];
static __device__ __align__(256) int   d_off [NN + 1];
static __device__ __align__(256) int   d_cur [NN];
static __device__ __align__(256) int   d_csr [EE];
static __device__ __align__(256) int   d_bsum [MAXBLK];
static __device__ __align__(256) int   d_bsum2[MAXBLK];
static __device__ __align__(256) float d_dinv[NN];
static __device__ __align__(256) float d_Hs [(size_t)NN * HID];  // x@W1 (unscaled)
static __device__ __align__(256) float d_H1 [(size_t)NN * HID];  // leaky(agg1)
static __device__ __align__(256) float d_Gs [(size_t)NN * HID];  // dinv*(H1@Wcat)
static __device__ __align__(256) float d_Wcat[HID * HID];

// ---------------- tf32 / async helpers ----------------
static __device__ __forceinline__ uint32_t f2tf32(float f) {
    uint32_t r;
    asm("cvt.rna.tf32.f32 %0, %1;" : "=r"(r) : "f"(f));
    return r;
}
static __device__ __forceinline__ uint32_t bits2tf32(uint32_t b) {
    uint32_t r;
    asm("cvt.rna.tf32.f32 %0, %1;" : "=r"(r) : "f"(__uint_as_float(b)));
    return r;
}
static __device__ __forceinline__ void mma_tf32_16x8x8(
    float& c0, float& c1, float& c2, float& c3,
    uint32_t a0, uint32_t a1, uint32_t a2, uint32_t a3,
    uint32_t b0, uint32_t b1) {
    asm volatile(
        "mma.sync.aligned.m16n8k8.row.col.f32.tf32.tf32.f32 "
        "{%0,%1,%2,%3}, {%4,%5,%6,%7}, {%8,%9}, {%0,%1,%2,%3};"
        : "+f"(c0), "+f"(c1), "+f"(c2), "+f"(c3)
        : "r"(a0), "r"(a1), "r"(a2), "r"(a3), "r"(b0), "r"(b1));
}
static __device__ __forceinline__ void cp16(void* smem_dst, const void* gsrc) {
    uint32_t s = (uint32_t)__cvta_generic_to_shared(smem_dst);
    asm volatile("cp.async.ca.shared.global [%0], [%1], 16;"
                 :: "r"(s), "l"(gsrc) : "memory");
}
static __device__ __forceinline__ void cp_commit() {
    asm volatile("cp.async.commit_group;" ::: "memory");
}
static __device__ __forceinline__ void cp_wait0() {
    asm volatile("cp.async.wait_group 0;" ::: "memory");
}

// ---------------- graph preprocessing ----------------
__global__ void k_zero_deg(int n) {
    int i = blockIdx.x * blockDim.x + threadIdx.x;
    if (i < n) d_degi[i] = 0;
}
__global__ void k_degcnt(const int* __restrict__ dst, int e) {
    int i = blockIdx.x * blockDim.x + threadIdx.x;
    if (i < e) atomicAdd(&d_degi[dst[i]], 1);
}
__global__ void k_dinv(int n) {
    int i = blockIdx.x * blockDim.x + threadIdx.x;
    if (i < n) d_dinv[i] = rsqrtf((float)(d_degi[i] + 1));  // +1 self loop
}
__global__ void k_scanA(int n) {
    __shared__ int sm[SCAN_B];
    int b = blockIdx.x, t = threadIdx.x, gi = b * SCAN_B + t;
    int v = (gi < n) ? d_degi[gi] : 0;
    sm[t] = v; __syncthreads();
    #pragma unroll
    for (int s = 1; s < SCAN_B; s <<= 1) {
        int u = (t >= s) ? sm[t - s] : 0;
        __syncthreads(); sm[t] += u; __syncthreads();
    }
    if (gi < n) d_off[gi + 1] = sm[t];
    if (t == SCAN_B - 1) d_bsum[b] = sm[t];
}
__global__ void k_scanB(int nblk) {
    __shared__ int sm[MAXBLK];
    int t = threadIdx.x;
    int v = (t < nblk) ? d_bsum[t] : 0;
    sm[t] = v; __syncthreads();
    #pragma unroll
    for (int s = 1; s < MAXBLK; s <<= 1) {
        int u = (t >= s) ? sm[t - s] : 0;
        __syncthreads(); sm[t] += u; __syncthreads();
    }
    if (t < nblk) d_bsum2[t] = sm[t] - v;
    if (t == 0) d_off[0] = 0;
}
__global__ void k_scanC(int n) {
    int b = blockIdx.x, t = threadIdx.x, gi = b * SCAN_B + t;
    if (gi < n) {
        int o = d_off[gi + 1] + d_bsum2[b];
        d_off[gi + 1] = o;
        d_cur[gi] = o - d_degi[gi];
    }
}
__global__ void k_scatter(const int* __restrict__ src,
                          const int* __restrict__ dst, int e) {
    int i = blockIdx.x * blockDim.x + threadIdx.x;
    if (i < e) {
        int d = dst[i];
        int pos = atomicAdd(&d_cur[d], 1);
        d_csr[pos] = src[i];
    }
}
__global__ void k_build_wcat(const float* __restrict__ Wmu,
                             const float* __restrict__ Wlv) {
    int i = blockIdx.x * blockDim.x + threadIdx.x;
    if (i < HID * HID) {
        int k = i / HID, c = i % HID;
        d_Wcat[i] = (c < OUTC) ? Wmu[k * OUTC + c] : Wlv[k * OUTC + (c - OUTC)];
    }
}

// -------- tf32 tensor-core GEMM: C[M,128] = A[M,K] @ B[K,128] [*dinv] --------
// 256 thr = 8 warps (2M x 4N), warp tile 64x32, BK=32 (4 k8 steps / barrier).
// A: LDG->cvt->STS (2-stage reg staged). B: cp.async fp32, cvt at fragment load.
template <int K>
__global__ void __launch_bounds__(256)
k_gemm(const float* __restrict__ A, const float* __restrict__ B,
       float* __restrict__ C, const float* __restrict__ dinv, int M) {
    constexpr int BM = 128, BN = 128, BK = 32;
    constexpr int NIT = K / BK;
    constexpr int ASTR = 36, BSTR = 136;
    extern __shared__ uint32_t dyn[];
    uint32_t* sA = dyn;                         // 2 x 128 x 36
    uint32_t* sB = dyn + 2 * BM * ASTR;         // 2 x 32 x 136

    const int tid  = threadIdx.x;
    const int lane = tid & 31;
    const int wid  = tid >> 5;
    const int wm   = wid & 1;
    const int wn   = wid >> 1;
    const int gid  = lane >> 2;
    const int tq   = lane & 3;
    const int row0 = blockIdx.x * BM;

    float4 av[4];
    auto gloadA = [&](int it) {
        int k0 = it * BK;
        #pragma unroll
        for (int i = 0; i < 4; i++) {
            int idx = tid + i * 256;
            int r = idx >> 3, c0 = (idx & 7) * 4;
            int gr = row0 + r;
            av[i] = (gr < M)
                ? *(const float4*)(A + (size_t)gr * K + k0 + c0)
                : make_float4(0.f, 0.f, 0.f, 0.f);
        }
    };
    auto stsA = [&](int b) {
        #pragma unroll
        for (int i = 0; i < 4; i++) {
            int idx = tid + i * 256;
            int r = idx >> 3, c0 = (idx & 7) * 4;
            uint4 t = make_uint4(f2tf32(av[i].x), f2tf32(av[i].y),
                                 f2tf32(av[i].z), f2tf32(av[i].w));
            *(uint4*)&sA[b * BM * ASTR + r * ASTR + c0] = t;
        }
    };
    auto cpB = [&](int it, int b) {
        #pragma unroll
        for (int i = 0; i < 4; i++) {
            int idx = tid + i * 256;
            int r = idx >> 5, c0 = (idx & 31) * 4;
            cp16(&sB[b * BK * BSTR + r * BSTR + c0],
                 B + (size_t)(it * BK + r) * BN + c0);
        }
        cp_commit();
    };

    float acc[4][4][4] = {};

    gloadA(0);
    cpB(0, 0);
    stsA(0);
    cp_wait0();
    __syncthreads();

    int buf = 0;
    for (int it = 0; it < NIT; it++) {
        if (it + 1 < NIT) {
            gloadA(it + 1);            // LDG in flight during MMA
            cpB(it + 1, buf ^ 1);      // cp.async in flight during MMA
        }
        const uint32_t* pa = &sA[buf * BM * ASTR];
        const uint32_t* pb = &sB[buf * BK * BSTR];
        #pragma unroll
        for (int ks = 0; ks < 4; ks++) {
            const int kk = ks * 8;
            uint32_t af[4][4], bf[4][2];
            #pragma unroll
            for (int mt = 0; mt < 4; mt++) {
                int m = wm * 64 + mt * 16 + gid;
                af[mt][0] = pa[(m    ) * ASTR + kk + tq];
                af[mt][1] = pa[(m + 8) * ASTR + kk + tq];
                af[mt][2] = pa[(m    ) * ASTR + kk + tq + 4];
                af[mt][3] = pa[(m + 8) * ASTR + kk + tq + 4];
            }
            #pragma unroll
            for (int nt = 0; nt < 4; nt++) {
                int nn = wn * 32 + nt * 8 + gid;
                bf[nt][0] = bits2tf32(pb[(kk + tq    ) * BSTR + nn]);
                bf[nt][1] = bits2tf32(pb[(kk + tq + 4) * BSTR + nn]);
            }
            #pragma unroll
            for (int mt = 0; mt < 4; mt++)
                #pragma unroll
                for (int nt = 0; nt < 4; nt++)
                    mma_tf32_16x8x8(acc[mt][nt][0], acc[mt][nt][1],
                                    acc[mt][nt][2], acc[mt][nt][3],
                                    af[mt][0], af[mt][1], af[mt][2], af[mt][3],
                                    bf[nt][0], bf[nt][1]);
        }
        if (it + 1 < NIT) {
            stsA(buf ^ 1);
            cp_wait0();
        }
        __syncthreads();
        buf ^= 1;
    }

    #pragma unroll
    for (int mt = 0; mt < 4; mt++) {
        int ra = row0 + wm * 64 + mt * 16 + gid;
        int rb = ra + 8;
        #pragma unroll
        for (int nt = 0; nt < 4; nt++) {
            int col = wn * 32 + nt * 8 + 2 * tq;
            if (ra < M) {
                float s = dinv ? dinv[ra] : 1.0f;
                *(float2*)(C + (size_t)ra * BN + col) =
                    make_float2(acc[mt][nt][0] * s, acc[mt][nt][1] * s);
            }
            if (rb < M) {
                float s = dinv ? dinv[rb] : 1.0f;
                *(float2*)(C + (size_t)rb * BN + col) =
                    make_float2(acc[mt][nt][2] * s, acc[mt][nt][3] * s);
            }
        }
    }
}

#define GEMM_SMEM ((2 * 128 * 36 + 2 * 32 * 136) * 4)   // 71680 B

// -------- agg1: warp per node, MLP-4 gather; Hs unscaled --------
__global__ void k_agg1(const float* __restrict__ b1, int n) {
    int d = (blockIdx.x * blockDim.x + threadIdx.x) >> 5;
    int lane = threadIdx.x & 31;
    if (d >= n) return;
    const float4* base = (const float4*)d_Hs;
    float sd = d_dinv[d];
    float4 acc = base[(size_t)d * 32 + lane];           // self
    acc.x *= sd; acc.y *= sd; acc.z *= sd; acc.w *= sd;
    int beg = d_off[d], end = d_off[d + 1];
    for (int k = beg; k < end; k += 32) {
        int rem = end - k; if (rem > 32) rem = 32;
        int   s  = (lane < rem) ? d_csr[k + lane] : 0;
        float sv = (lane < rem) ? d_dinv[s] : 0.f;
        int j = 0;
        for (; j + 4 <= rem; j += 4) {
            int s0 = __shfl_sync(0xffffffffu, s, j);
            int s1 = __shfl_sync(0xffffffffu, s, j + 1);
            int s2 = __shfl_sync(0xffffffffu, s, j + 2);
            int s3 = __shfl_sync(0xffffffffu, s, j + 3);
            float d0 = __shfl_sync(0xffffffffu, sv, j);
            float d1 = __shfl_sync(0xffffffffu, sv, j + 1);
            float d2 = __shfl_sync(0xffffffffu, sv, j + 2);
            float d3 = __shfl_sync(0xffffffffu, sv, j + 3);
            float4 v0 = base[(size_t)s0 * 32 + lane];
            float4 v1 = base[(size_t)s1 * 32 + lane];
            float4 v2 = base[(size_t)s2 * 32 + lane];
            float4 v3 = base[(size_t)s3 * 32 + lane];
            acc.x += v0.x * d0 + v1.x * d1 + v2.x * d2 + v3.x * d3;
            acc.y += v0.y * d0 + v1.y * d1 + v2.y * d2 + v3.y * d3;
            acc.z += v0.z * d0 + v1.z * d1 + v2.z * d2 + v3.z * d3;
            acc.w += v0.w * d0 + v1.w * d1 + v2.w * d2 + v3.w * d3;
        }
        for (; j < rem; j++) {
            int   sj = __shfl_sync(0xffffffffu, s,  j);
            float dv = __shfl_sync(0xffffffffu, sv, j);
            float4 v = base[(size_t)sj * 32 + lane];
            acc.x += v.x * dv; acc.y += v.y * dv;
            acc.z += v.z * dv; acc.w += v.w * dv;
        }
    }
    float4 bb = *(const float4*)(b1 + lane * 4);
    float4 r;
    r.x = acc.x * sd + bb.x; r.y = acc.y * sd + bb.y;
    r.z = acc.z * sd + bb.z; r.w = acc.w * sd + bb.w;
    r.x = r.x >= 0.f ? r.x : 0.01f * r.x;
    r.y = r.y >= 0.f ? r.y : 0.01f * r.y;
    r.z = r.z >= 0.f ? r.z : 0.01f * r.z;
    r.w = r.w >= 0.f ? r.w : 0.01f * r.w;
    *(float4*)(d_H1 + (size_t)d * HID + lane * 4) = r;
}

// -------- agg2: warp per node, MLP-4 gather, Gs pre-scaled --------
__global__ void k_agg2(const float* __restrict__ bmu,
                       const float* __restrict__ blv,
                       float* __restrict__ mu, float* __restrict__ lv, int n) {
    int d = (blockIdx.x * blockDim.x + threadIdx.x) >> 5;
    int lane = threadIdx.x & 31;
    if (d >= n) return;
    const float4* base = (const float4*)d_Gs;
    float4 acc = base[(size_t)d * 32 + lane];           // self (pre-scaled)
    int beg = d_off[d], end = d_off[d + 1];
    for (int k = beg; k < end; k += 32) {
        int rem = end - k; if (rem > 32) rem = 32;
        int s = (lane < rem) ? d_csr[k + lane] : 0;
        int j = 0;
        for (; j + 4 <= rem; j += 4) {
            int s0 = __shfl_sync(0xffffffffu, s, j);
            int s1 = __shfl_sync(0xffffffffu, s, j + 1);
            int s2 = __shfl_sync(0xffffffffu, s, j + 2);
            int s3 = __shfl_sync(0xffffffffu, s, j + 3);
            float4 v0 = base[(size_t)s0 * 32 + lane];
            float4 v1 = base[(size_t)s1 * 32 + lane];
            float4 v2 = base[(size_t)s2 * 32 + lane];
            float4 v3 = base[(size_t)s3 * 32 + lane];
            acc.x += v0.x + v1.x + v2.x + v3.x;
            acc.y += v0.y + v1.y + v2.y + v3.y;
            acc.z += v0.z + v1.z + v2.z + v3.z;
            acc.w += v0.w + v1.w + v2.w + v3.w;
        }
        for (; j < rem; j++) {
            int sj = __shfl_sync(0xffffffffu, s, j);
            float4 v = base[(size_t)sj * 32 + lane];
            acc.x += v.x; acc.y += v.y; acc.z += v.z; acc.w += v.w;
        }
    }
    float sc = d_dinv[d];
    float4 bb = (lane < 16) ? *(const float4*)(bmu + lane * 4)
                            : *(const float4*)(blv + (lane - 16) * 4);
    float4 r;
    r.x = acc.x * sc + bb.x; r.y = acc.y * sc + bb.y;
    r.z = acc.z * sc + bb.z; r.w = acc.w * sc + bb.w;
    float* p = (lane < 16) ? (mu + (size_t)d * OUTC + lane * 4)
                           : (lv + (size_t)d * OUTC + (lane - 16) * 4);
    *(float4*)p = r;
}

// ---------------- launch ----------------
extern "C" void kernel_launch(void* const* d_in, const int* in_sizes, int n_in,
                              void* d_out, int out_size) {
    const float* x   = (const float*)d_in[0];
    const int*   ei  = (const int*)d_in[1];     // int32 (JAX x64 disabled)
    const float* W1  = (const float*)d_in[2];
    const float* b1  = (const float*)d_in[3];
    const float* Wmu = (const float*)d_in[4];
    const float* bmu = (const float*)d_in[5];
    const float* Wlv = (const float*)d_in[6];
    const float* blv = (const float*)d_in[7];

    const int e = in_sizes[1] / 2;
    const int n = in_sizes[0] / INC;
    const int* src = ei;
    const int* dst = ei + e;

    float* mu = (float*)d_out;
    float* lv = mu + (size_t)n * OUTC;

    float *hs_p, *h1_p, *gs_p, *wcat_p, *dinv_p;
    cudaGetSymbolAddress((void**)&hs_p,   d_Hs);
    cudaGetSymbolAddress((void**)&h1_p,   d_H1);
    cudaGetSymbolAddress((void**)&gs_p,   d_Gs);
    cudaGetSymbolAddress((void**)&wcat_p, d_Wcat);
    cudaGetSymbolAddress((void**)&dinv_p, d_dinv);

    static cudaStream_t s1 = nullptr;
    static cudaEvent_t  evFork = nullptr, evJoin = nullptr;
    if (!s1) {
        cudaStreamCreateWithFlags(&s1, cudaStreamNonBlocking);
        cudaEventCreateWithFlags(&evFork, cudaEventDisableTiming);
        cudaEventCreateWithFlags(&evJoin, cudaEventDisableTiming);
        cudaFuncSetAttribute(k_gemm<INC>,
            cudaFuncAttributeMaxDynamicSharedMemorySize, GEMM_SMEM);
        cudaFuncSetAttribute(k_gemm<HID>,
            cudaFuncAttributeMaxDynamicSharedMemorySize, GEMM_SMEM);
    }

    const int T = 256;
    const int nblk = (n + SCAN_B - 1) / SCAN_B;
    const int gblk = (n + 127) / 128;

    // fork: graph prep on s1 concurrent with GEMM1 on main stream.
    // GEMM1 stays at launch slot 4 so ncu captures it.
    cudaEventRecord(evFork, 0);
    cudaStreamWaitEvent(s1, evFork, 0);

    k_zero_deg<<<(n + T - 1) / T, T, 0, s1>>>(n);
    k_degcnt<<<(e + T - 1) / T, T, 0, s1>>>(dst, e);
    k_dinv<<<(n + T - 1) / T, T, 0, s1>>>(n);

    // GEMM1 (tf32 tensor cores, unscaled) — 4th launch (profiled)
    k_gemm<INC><<<gblk, 256, GEMM_SMEM>>>(x, W1, hs_p, nullptr, n);

    k_scanA<<<nblk, SCAN_B, 0, s1>>>(n);
    k_scanB<<<1, MAXBLK, 0, s1>>>(nblk);
    k_scanC<<<nblk, SCAN_B, 0, s1>>>(n);
    k_scatter<<<(e + T - 1) / T, T, 0, s1>>>(src, dst, e);
    k_build_wcat<<<(HID * HID + T - 1) / T, T, 0, s1>>>(Wmu, Wlv);

    // join
    cudaEventRecord(evJoin, s1);
    cudaStreamWaitEvent(0, evJoin, 0);

    // agg1 (folds all dinv scaling), GEMM2 (tf32), agg2
    k_agg1<<<(n * 32 + T - 1) / T, T>>>(b1, n);
    k_gemm<HID><<<gblk, 256, GEMM_SMEM>>>(h1_p, wcat_p, gs_p, dinv_p, n);
    k_agg2<<<(n * 32 + T - 1) / T, T>>>(bmu, blv, mu, lv, n);
}